// round 3
// baseline (speedup 1.0000x reference)
#include <cuda_runtime.h>

typedef unsigned long long ull;

// ---------------- problem constants ----------------
#define BB   8
#define TT   8
#define CC   32
#define HH   16
#define WW   28
#define HWp  448
#define NHh  4
#define DKk  8
#define SG   2

// ---------------- device scratch ----------------
__device__ __align__(16) float g_q   [BB*TT*CC*HWp];              // [bt][o][p]
__device__ __align__(16) float g_kv  [BB*NHh*TT*HWp*16];          // [b][h][s][p][k0..7 v0..7]
__device__ __align__(16) float g_tout[SG*BB*TT*HWp*NHh*DKk];      // [ss][bt][p][h*8+c]
__device__ __align__(16) float g_sum [SG*BB*TT*HWp*NHh];          // [ss][bt][p][h]
__device__ __align__(16) float g_mx  [SG*BB*TT*HWp*NHh];

// ---------------- packed f32x2 helpers ----------------
__device__ __forceinline__ ull pack2(float lo, float hi){ ull r; asm("mov.b64 %0,{%1,%2};":"=l"(r):"f"(lo),"f"(hi)); return r; }
__device__ __forceinline__ void unpack2(ull v, float& lo, float& hi){ asm("mov.b64 {%0,%1},%2;":"=f"(lo),"=f"(hi):"l"(v)); }
__device__ __forceinline__ ull pack2i(int lo, int hi){ ull r; asm("mov.b64 %0,{%1,%2};":"=l"(r):"r"(lo),"r"(hi)); return r; }
__device__ __forceinline__ void unpack2i(ull v, int& lo, int& hi){ asm("mov.b64 {%0,%1},%2;":"=r"(lo),"=r"(hi):"l"(v)); }
__device__ __forceinline__ ull fma2(ull a, ull b, ull c){ ull d; asm("fma.rn.f32x2 %0,%1,%2,%3;":"=l"(d):"l"(a),"l"(b),"l"(c)); return d; }
__device__ __forceinline__ ull add2(ull a, ull b){ ull d; asm("add.rn.f32x2 %0,%1,%2;":"=l"(d):"l"(a),"l"(b)); return d; }
__device__ __forceinline__ ull mul2(ull a, ull b){ ull d; asm("mul.rn.f32x2 %0,%1,%2;":"=l"(d):"l"(a),"l"(b)); return d; }

__device__ __forceinline__ float exp2_fast(float x) {
    float z = __fadd_rn(x, 12582912.0f);
    float n = __fadd_rn(z, -12582912.0f);
    float f = x - n;
    int   sb = __float_as_int(z) * 8388608 + 0x3F800000;
    float p = fmaf(fmaf(fmaf(fmaf(0.0096181291f, f, 0.055504109f),
                             f, 0.24022651f), f, 0.69314718f), f, 1.0f);
    return p * __int_as_float(sb);
}

__device__ __forceinline__ ull exp2x2(ull x) {
    const ull C2  = pack2( 12582912.0f,  12582912.0f);
    const ull nC2 = pack2(-12582912.0f, -12582912.0f);
    const ull n1  = pack2(-1.0f, -1.0f);
    const ull c4  = pack2(0.0096181291f, 0.0096181291f);
    const ull c3  = pack2(0.055504109f,  0.055504109f);
    const ull c2  = pack2(0.24022651f,   0.24022651f);
    const ull c1  = pack2(0.69314718f,   0.69314718f);
    const ull one = pack2(1.0f, 1.0f);
    ull z = add2(x, C2);
    ull n = add2(z, nC2);
    ull f = fma2(n, n1, x);
    ull p = fma2(fma2(fma2(fma2(c4, f, c3), f, c2), f, c1), f, one);
    int zl, zh; unpack2i(z, zl, zh);
    int sl = zl * 8388608 + 0x3F800000;
    int sh = zh * 8388608 + 0x3F800000;
    return mul2(p, pack2i(sl, sh));
}

// ---------------- K1: Q/K/V projections ----------------
__global__ __launch_bounds__(128)
void k_proj(const float* __restrict__ first, const float* __restrict__ x,
            const float* __restrict__ Wq, const float* __restrict__ Wk,
            const float* __restrict__ Wv) {
    __shared__ float swq[1024], swk[1024], swv[1024];
    int tid = threadIdx.x;
    for (int i = tid; i < 1024; i += 128) { swq[i]=Wq[i]; swk[i]=Wk[i]; swv[i]=Wv[i]; }
    __syncthreads();

    int gi = blockIdx.x * 128 + tid;              // [0, 28672)
    int p  = gi % HWp;
    int bt = gi / HWp;
    int b  = bt >> 3, t = bt & 7;

    const float* fb = first + (size_t)bt * CC * HWp + p;
    const float* xb = x     + (size_t)bt * CC * HWp + p;
    ull fp[16], xp[16];
    #pragma unroll
    for (int j = 0; j < 16; j++) {
        fp[j] = pack2(fb[(2*j)*HWp], fb[(2*j+1)*HWp]);
        xp[j] = pack2(xb[(2*j)*HWp], xb[(2*j+1)*HWp]);
    }

    #pragma unroll
    for (int h = 0; h < NHh; h++) {
        float kr[8], vr[8];
        #pragma unroll
        for (int c8 = 0; c8 < 8; c8++) {
            int o = h*8 + c8;
            const ull* wq = (const ull*)&swq[o*CC];
            const ull* wk = (const ull*)&swk[o*CC];
            const ull* wv = (const ull*)&swv[o*CC];
            ull aq = mul2(fp[0], wq[0]);
            ull ak = mul2(xp[0], wk[0]);
            ull av = mul2(xp[0], wv[0]);
            #pragma unroll
            for (int j = 1; j < 16; j++) {
                aq = fma2(fp[j], wq[j], aq);
                ak = fma2(xp[j], wk[j], ak);
                av = fma2(xp[j], wv[j], av);
            }
            float l, hh;
            unpack2(aq, l, hh);
            g_q[((size_t)bt*CC + o)*HWp + p] = l + hh;
            unpack2(ak, l, hh); kr[c8] = l + hh;
            unpack2(av, l, hh); vr[c8] = l + hh;
        }
        float* dst = g_kv + ((((size_t)b*NHh + h)*TT + t)*HWp + p)*16;
        *(float4*)(dst)      = make_float4(kr[0], kr[1], kr[2], kr[3]);
        *(float4*)(dst + 4)  = make_float4(kr[4], kr[5], kr[6], kr[7]);
        *(float4*)(dst + 8)  = make_float4(vr[0], vr[1], vr[2], vr[3]);
        *(float4*)(dst + 12) = make_float4(vr[4], vr[5], vr[6], vr[7]);
    }
}

// ---------------- K2: per-(b,t,head) LayerNorm of q ----------------
__global__ __launch_bounds__(128)
void k_ln(const float* __restrict__ gamma, const float* __restrict__ beta) {
    const int N = DKk * HWp;                      // 3584
    float* base = g_q + (size_t)blockIdx.x * N;   // blocks = B*T*NH = 256
    int tid = threadIdx.x;

    float vals[28];
    float s = 0.f, sq = 0.f;
    #pragma unroll
    for (int i = 0; i < 28; i++) {
        float v = base[tid + i*128];
        vals[i] = v; s += v; sq = fmaf(v, v, sq);
    }
    #pragma unroll
    for (int o = 16; o > 0; o >>= 1) {
        s  += __shfl_xor_sync(0xFFFFFFFFu, s,  o);
        sq += __shfl_xor_sync(0xFFFFFFFFu, sq, o);
    }
    __shared__ float shs[4], shq[4];
    if ((tid & 31) == 0) { shs[tid>>5] = s; shq[tid>>5] = sq; }
    __syncthreads();
    s  = shs[0]+shs[1]+shs[2]+shs[3];
    sq = shq[0]+shq[1]+shq[2]+shq[3];

    float mu   = s * (1.0f/3584.0f);
    float var  = fmaf(-mu, mu, sq * (1.0f/3584.0f));
    float rstd = rsqrtf(var + 1e-5f);
    #pragma unroll
    for (int i = 0; i < 28; i++) {
        int idx = tid + i*128;
        base[idx] = fmaf((vals[i]-mu)*rstd, gamma[idx], beta[idx]);
    }
}

// ---------------- K3: dilated local attention ----------------
// grid = 512: bid bits [ys(1)][sg(1)][head(2)][tp(2)][b(3)], head in bits 2:3 so
// co-resident blocks (stride 148, bit2 set) rotate head -> per-SM head mix.
__global__ __launch_bounds__(224, 3)
void k_attn() {
    int bid = blockIdx.x;
    int ys   = bid & 1;
    int sg   = (bid >> 1) & 1;
    int head = (bid >> 2) & 3;
    int tp   = (bid >> 4) & 3;
    int b    = bid >> 6;
    const int dil = 2*head + 1;

    __shared__ float4 skv[HWp*4];                 // 28672 B, swizzled granules

    int tid = threadIdx.x;
    int row = tid / WW;
    int xq  = tid - row*WW;
    int y   = ys*8 + row;
    int t0  = tp*2;
    int p   = y*WW + xq;

    const float INV = 0.35355339059327373f;       // 1/sqrt(C/NH)
    const float L2E = 1.4426950408889634f;

    // q packed over channel pairs: qp[t][j] = (q[2j], q[2j+1])
    ull qp[2][4];
    #pragma unroll
    for (int t = 0; t < 2; t++) {
        const float* qb = g_q + ((size_t)(b*TT + t0 + t)*CC + head*DKk)*HWp + p;
        #pragma unroll
        for (int j = 0; j < 4; j++)
            qp[t][j] = pack2(qb[(2*j)*HWp], qb[(2*j+1)*HWp]);
    }

    ull tout[2][4];
    #pragma unroll
    for (int t = 0; t < 2; t++)
        #pragma unroll
        for (int j = 0; j < 4; j++) tout[t][j] = pack2(0.f, 0.f);
    ull summ = pack2(0.f, 0.f);
    float mx0 = -126.f, mx1 = -126.f;

    const ulonglong2* skv2 = (const ulonglong2*)skv;

    #pragma unroll 1
    for (int si = 0; si < 4; si++) {
        if (si) __syncthreads();
        {   // stage interleaved kv page for s = sg*4+si, swizzled
            const float4* src = (const float4*)(g_kv +
                ((((size_t)b*NHh + head)*TT + (sg*4 + si))*HWp)*16);
            #pragma unroll
            for (int r = 0; r < 8; r++) {
                int g = tid + r*224;
                skv[g ^ ((g >> 3) & 7)] = src[g];
            }
        }
        __syncthreads();

        #pragma unroll 1
        for (int oy = -3; oy <= 3; oy++) {
            int yy = y + oy*dil;
            if ((unsigned)yy < (unsigned)HH) {
                int rb = yy * WW;
                #pragma unroll
                for (int i = 0; i < 7; i++) {
                    const int oxd = (i - 3) * dil;        // compile-time per instance
                    int xx = xq + oxd;
                    bool vx = (unsigned)xx < (unsigned)WW;
                    int sp = rb + (vx ? xx : 0);
                    float ws = vx ? INV : 0.f;
                    float s2 = vx ? (INV * L2E) : 0.f;
                    float bv = vx ? -32.f : -126.f;

                    int gb = 4*sp;
                    int m  = (sp >> 1) & 7;
                    ulonglong2 kA = skv2[(gb    ) ^ m];   // (k0,k1),(k2,k3)
                    ulonglong2 kB = skv2[(gb + 1) ^ m];   // (k4,k5),(k6,k7)
                    ulonglong2 vA = skv2[(gb + 2) ^ m];   // (v0,v1),(v2,v3)
                    ulonglong2 vB = skv2[(gb + 3) ^ m];   // (v4,v5),(v6,v7)

                    ull d0 = mul2(qp[0][0], kA.x);
                    ull d1 = mul2(qp[1][0], kA.x);
                    d0 = fma2(qp[0][1], kA.y, d0);
                    d1 = fma2(qp[1][1], kA.y, d1);
                    d0 = fma2(qp[0][2], kB.x, d0);
                    d1 = fma2(qp[1][2], kB.x, d1);
                    d0 = fma2(qp[0][3], kB.y, d0);
                    d1 = fma2(qp[1][3], kB.y, d1);

                    float l, h;
                    unpack2(d0, l, h); float sc0 = l + h;
                    unpack2(d1, l, h); float sc1 = l + h;

                    float w0 = sc0 * ws, w1 = sc1 * ws;
                    ull wp0 = pack2(w0, w0), wp1 = pack2(w1, w1);
                    tout[0][0] = fma2(wp0, vA.x, tout[0][0]);
                    tout[1][0] = fma2(wp1, vA.x, tout[1][0]);
                    tout[0][1] = fma2(wp0, vA.y, tout[0][1]);
                    tout[1][1] = fma2(wp1, vA.y, tout[1][1]);
                    tout[0][2] = fma2(wp0, vB.x, tout[0][2]);
                    tout[1][2] = fma2(wp1, vB.x, tout[1][2]);
                    tout[0][3] = fma2(wp0, vB.y, tout[0][3]);
                    tout[1][3] = fma2(wp1, vB.y, tout[1][3]);

                    float a0 = fmaf(sc0, s2, bv);
                    float a1 = fmaf(sc1, s2, bv);
                    mx0 = fmaxf(mx0, a0);
                    mx1 = fmaxf(mx1, a1);
                    summ = add2(summ, exp2x2(pack2(a0, a1)));
                }
            }
        }
    }

    float sl, sh; unpack2(summ, sl, sh);
    #pragma unroll
    for (int t = 0; t < 2; t++) {
        int bt = b*TT + t0 + t;
        float e[8];
        #pragma unroll
        for (int j = 0; j < 4; j++) unpack2(tout[t][j], e[2*j], e[2*j+1]);
        float* tb = g_tout + ((size_t)(sg*(BB*TT) + bt)*HWp + p)*(NHh*DKk) + head*DKk;
        *(float4*)(tb)     = make_float4(e[0], e[1], e[2], e[3]);
        *(float4*)(tb + 4) = make_float4(e[4], e[5], e[6], e[7]);
        size_t mi = ((size_t)(sg*(BB*TT) + bt)*HWp + p)*NHh + head;
        g_sum[mi] = t ? sh : sl;
        g_mx[mi]  = t ? mx1 : mx0;
    }
}

// ---------------- K4: combine + M_S + output projection (o split 2 ways) ----------------
__global__ __launch_bounds__(128)
void k_out(const float* __restrict__ Wo, float* __restrict__ out) {
    __shared__ float swo[1024];
    int tid = threadIdx.x;
    for (int i = tid; i < 1024; i += 128) swo[i] = Wo[i];
    __syncthreads();

    int gi = blockIdx.x * 128 + tid;              // [0, 57344)
    int p  = gi % HWp;
    int r  = gi / HWp;                            // [0, 128)
    int bt = r >> 1;
    int oh = (r & 1) * 16;

    const float4* ta = (const float4*)(g_tout + ((size_t)bt*HWp + p)*(NHh*DKk));
    const float4* tb = (const float4*)(g_tout + ((size_t)(BB*TT + bt)*HWp + p)*(NHh*DKk));
    ull tc2[16];
    #pragma unroll
    for (int j = 0; j < 8; j++) {
        float4 u = ta[j], v = tb[j];
        tc2[2*j]   = pack2(u.x + v.x, u.y + v.y);
        tc2[2*j+1] = pack2(u.z + v.z, u.w + v.w);
    }

    float4 s0 = *(const float4*)(g_sum + ((size_t)bt*HWp + p)*NHh);
    float4 s1 = *(const float4*)(g_sum + ((size_t)(BB*TT + bt)*HWp + p)*NHh);
    float4 m0 = *(const float4*)(g_mx  + ((size_t)bt*HWp + p)*NHh);
    float4 m1 = *(const float4*)(g_mx  + ((size_t)(BB*TT + bt)*HWp + p)*NHh);

    float MS;
    {
        float sh0 = s0.x + s1.x, sh1 = s0.y + s1.y, sh2 = s0.z + s1.z, sh3 = s0.w + s1.w;
        float mh0 = fmaxf(m0.x, m1.x), mh1 = fmaxf(m0.y, m1.y);
        float mh2 = fmaxf(m0.z, m1.z), mh3 = fmaxf(m0.w, m1.w);
        MS =           __fdividef(exp2_fast(mh0), sh0);
        MS = fmaxf(MS, __fdividef(exp2_fast(mh1), sh1));
        MS = fmaxf(MS, __fdividef(exp2_fast(mh2), sh2));
        MS = fmaxf(MS, __fdividef(exp2_fast(mh3), sh3));
    }

    float* ob = out + (size_t)bt * CC * HWp + p;
    #pragma unroll
    for (int o = oh; o < oh + 16; o++) {
        const ull* wp = (const ull*)&swo[o*CC];
        ull acc = mul2(tc2[0], wp[0]);
        #pragma unroll
        for (int j = 1; j < 16; j++) acc = fma2(tc2[j], wp[j], acc);
        float l, h; unpack2(acc, l, h);
        ob[o*HWp] = (l + h) * MS;
    }
}

// ---------------- launcher ----------------
extern "C" void kernel_launch(void* const* d_in, const int* in_sizes, int n_in,
                              void* d_out, int out_size) {
    const float* first = (const float*)d_in[0];
    const float* x     = (const float*)d_in[1];
    const float* Wq    = (const float*)d_in[2];
    const float* Wk    = (const float*)d_in[3];
    const float* Wv    = (const float*)d_in[4];
    const float* Wo    = (const float*)d_in[5];
    const float* lng   = (const float*)d_in[6];
    const float* lnb   = (const float*)d_in[7];
    float* out = (float*)d_out;

    k_proj<<<224, 128>>>(first, x, Wq, Wk, Wv);
    k_ln<<<BB*TT*NHh, 128>>>(lng, lnb);
    k_attn<<<512, 224>>>();
    k_out<<<448, 128>>>(Wo, out);
}

// round 4
// speedup vs baseline: 1.1956x; 1.1956x over previous
#include <cuda_runtime.h>

typedef unsigned long long ull;

// ---------------- problem constants ----------------
#define BB   8
#define TT   8
#define CC   32
#define HH   16
#define WW   28
#define HWp  448
#define NHh  4
#define DKk  8
#define SGn  4           // s-groups (each attention block loops 2 timesteps)

// ---------------- device scratch ----------------
__device__ __align__(16) float g_q   [BB*TT*CC*HWp];              // [bt][o][p]
__device__ __align__(16) float g_kv  [BB*NHh*TT*HWp*16];          // [b][h][s][p][k0..7 v0..7]
__device__ __align__(16) float g_tout[SGn*BB*TT*CC*HWp];          // [ss][bt][h*8+c][p]  (p fastest!)
__device__ __align__(16) float g_sum [SGn*BB*TT*NHh*HWp];         // [ss][bt][h][p]
__device__ __align__(16) float g_mx  [SGn*BB*TT*NHh*HWp];

// ---------------- packed f32x2 helpers ----------------
__device__ __forceinline__ ull pack2(float lo, float hi){ ull r; asm("mov.b64 %0,{%1,%2};":"=l"(r):"f"(lo),"f"(hi)); return r; }
__device__ __forceinline__ void unpack2(ull v, float& lo, float& hi){ asm("mov.b64 {%0,%1},%2;":"=f"(lo),"=f"(hi):"l"(v)); }
__device__ __forceinline__ ull pack2i(int lo, int hi){ ull r; asm("mov.b64 %0,{%1,%2};":"=l"(r):"r"(lo),"r"(hi)); return r; }
__device__ __forceinline__ void unpack2i(ull v, int& lo, int& hi){ asm("mov.b64 {%0,%1},%2;":"=r"(lo),"=r"(hi):"l"(v)); }
__device__ __forceinline__ ull fma2(ull a, ull b, ull c){ ull d; asm("fma.rn.f32x2 %0,%1,%2,%3;":"=l"(d):"l"(a),"l"(b),"l"(c)); return d; }
__device__ __forceinline__ ull add2(ull a, ull b){ ull d; asm("add.rn.f32x2 %0,%1,%2;":"=l"(d):"l"(a),"l"(b)); return d; }
__device__ __forceinline__ ull mul2(ull a, ull b){ ull d; asm("mul.rn.f32x2 %0,%1,%2;":"=l"(d):"l"(a),"l"(b)); return d; }

__device__ __forceinline__ float exp2_fast(float x) {
    float z = __fadd_rn(x, 12582912.0f);
    float n = __fadd_rn(z, -12582912.0f);
    float f = x - n;
    int   sb = __float_as_int(z) * 8388608 + 0x3F800000;
    float p = fmaf(fmaf(fmaf(fmaf(0.0096181291f, f, 0.055504109f),
                             f, 0.24022651f), f, 0.69314718f), f, 1.0f);
    return p * __int_as_float(sb);
}

__device__ __forceinline__ ull exp2x2(ull x) {
    const ull C2  = pack2( 12582912.0f,  12582912.0f);
    const ull nC2 = pack2(-12582912.0f, -12582912.0f);
    const ull n1  = pack2(-1.0f, -1.0f);
    const ull c4  = pack2(0.0096181291f, 0.0096181291f);
    const ull c3  = pack2(0.055504109f,  0.055504109f);
    const ull c2  = pack2(0.24022651f,   0.24022651f);
    const ull c1  = pack2(0.69314718f,   0.69314718f);
    const ull one = pack2(1.0f, 1.0f);
    ull z = add2(x, C2);
    ull n = add2(z, nC2);
    ull f = fma2(n, n1, x);
    ull p = fma2(fma2(fma2(fma2(c4, f, c3), f, c2), f, c1), f, one);
    int zl, zh; unpack2i(z, zl, zh);
    int sl = zl * 8388608 + 0x3F800000;
    int sh = zh * 8388608 + 0x3F800000;
    return mul2(p, pack2i(sl, sh));
}

// ---------------- K1: Q/K/V projections ----------------
__global__ __launch_bounds__(128)
void k_proj(const float* __restrict__ first, const float* __restrict__ x,
            const float* __restrict__ Wq, const float* __restrict__ Wk,
            const float* __restrict__ Wv) {
    __shared__ float swq[1024], swk[1024], swv[1024];
    int tid = threadIdx.x;
    for (int i = tid; i < 1024; i += 128) { swq[i]=Wq[i]; swk[i]=Wk[i]; swv[i]=Wv[i]; }
    __syncthreads();

    int gi = blockIdx.x * 128 + tid;              // [0, 28672)
    int p  = gi % HWp;
    int bt = gi / HWp;
    int b  = bt >> 3, t = bt & 7;

    const float* fb = first + (size_t)bt * CC * HWp + p;
    const float* xb = x     + (size_t)bt * CC * HWp + p;
    ull fp[16], xp[16];
    #pragma unroll
    for (int j = 0; j < 16; j++) {
        fp[j] = pack2(fb[(2*j)*HWp], fb[(2*j+1)*HWp]);
        xp[j] = pack2(xb[(2*j)*HWp], xb[(2*j+1)*HWp]);
    }

    #pragma unroll
    for (int h = 0; h < NHh; h++) {
        float kr[8], vr[8];
        #pragma unroll
        for (int c8 = 0; c8 < 8; c8++) {
            int o = h*8 + c8;
            const ull* wq = (const ull*)&swq[o*CC];
            const ull* wk = (const ull*)&swk[o*CC];
            const ull* wv = (const ull*)&swv[o*CC];
            ull aq = mul2(fp[0], wq[0]);
            ull ak = mul2(xp[0], wk[0]);
            ull av = mul2(xp[0], wv[0]);
            #pragma unroll
            for (int j = 1; j < 16; j++) {
                aq = fma2(fp[j], wq[j], aq);
                ak = fma2(xp[j], wk[j], ak);
                av = fma2(xp[j], wv[j], av);
            }
            float l, hh;
            unpack2(aq, l, hh);
            g_q[((size_t)bt*CC + o)*HWp + p] = l + hh;
            unpack2(ak, l, hh); kr[c8] = l + hh;
            unpack2(av, l, hh); vr[c8] = l + hh;
        }
        float* dst = g_kv + ((((size_t)b*NHh + h)*TT + t)*HWp + p)*16;
        *(float4*)(dst)      = make_float4(kr[0], kr[1], kr[2], kr[3]);
        *(float4*)(dst + 4)  = make_float4(kr[4], kr[5], kr[6], kr[7]);
        *(float4*)(dst + 8)  = make_float4(vr[0], vr[1], vr[2], vr[3]);
        *(float4*)(dst + 12) = make_float4(vr[4], vr[5], vr[6], vr[7]);
    }
}

// ---------------- K2: per-(b,t,head) LayerNorm of q ----------------
__global__ __launch_bounds__(128)
void k_ln(const float* __restrict__ gamma, const float* __restrict__ beta) {
    const int N = DKk * HWp;                      // 3584
    float* base = g_q + (size_t)blockIdx.x * N;   // blocks = B*T*NH = 256
    int tid = threadIdx.x;

    float vals[28];
    float s = 0.f, sq = 0.f;
    #pragma unroll
    for (int i = 0; i < 28; i++) {
        float v = base[tid + i*128];
        vals[i] = v; s += v; sq = fmaf(v, v, sq);
    }
    #pragma unroll
    for (int o = 16; o > 0; o >>= 1) {
        s  += __shfl_xor_sync(0xFFFFFFFFu, s,  o);
        sq += __shfl_xor_sync(0xFFFFFFFFu, sq, o);
    }
    __shared__ float shs[4], shq[4];
    if ((tid & 31) == 0) { shs[tid>>5] = s; shq[tid>>5] = sq; }
    __syncthreads();
    s  = shs[0]+shs[1]+shs[2]+shs[3];
    sq = shq[0]+shq[1]+shq[2]+shq[3];

    float mu   = s * (1.0f/3584.0f);
    float var  = fmaf(-mu, mu, sq * (1.0f/3584.0f));
    float rstd = rsqrtf(var + 1e-5f);
    #pragma unroll
    for (int i = 0; i < 28; i++) {
        int idx = tid + i*128;
        base[idx] = fmaf((vals[i]-mu)*rstd, gamma[idx], beta[idx]);
    }
}

// ---------------- K3: dilated local attention ----------------
// grid = 1024: bid = [b(3)][ts(1)][sg(2)][head(2)][ys(2)]; head at bits 2:3
// so co-resident blocks mix dilations across SMs. 112 threads = 4 rows x 28.
// t-group = 4 (one kv read serves 4 query timesteps).
__global__ __launch_bounds__(112, 4)
void k_attn() {
    int bid  = blockIdx.x;
    int ys   = bid & 3;
    int head = (bid >> 2) & 3;
    int sg   = (bid >> 4) & 3;
    int ts   = (bid >> 6) & 1;
    int b    = bid >> 7;
    const int dil = 2*head + 1;

    __shared__ float4 skv[1800];                  // 1792 data granules + 4 zero + pad

    int tid = threadIdx.x;
    int row = tid / WW;                           // 0..3
    int xq  = tid - row*WW;
    int y   = ys*4 + row;
    int t0  = ts*4;
    int p   = y*WW + xq;

    if (tid < 4) skv[1792 + tid] = make_float4(0.f, 0.f, 0.f, 0.f);

    const float INV = 0.35355339059327373f;                 // 1/sqrt(C/NH)
    const float S2C = 0.35355339059327373f * 1.4426950408889634f;
    const ull INV2 = pack2(INV, INV);
    const ull S2_2 = pack2(S2C, S2C);

    // q: 4 timesteps x 8 channels as c-pairs
    ull qp[4][4];
    #pragma unroll
    for (int t = 0; t < 4; t++) {
        const float* qb = g_q + ((size_t)(b*TT + t0 + t)*CC + head*DKk)*HWp + p;
        #pragma unroll
        for (int j = 0; j < 4; j++)
            qp[t][j] = pack2(qb[(2*j)*HWp], qb[(2*j+1)*HWp]);
    }

    ull tout[4][4];
    #pragma unroll
    for (int t = 0; t < 4; t++)
        #pragma unroll
        for (int j = 0; j < 4; j++) tout[t][j] = pack2(0.f, 0.f);
    ull summ01 = pack2(0.f, 0.f), summ23 = pack2(0.f, 0.f);
    float mx0 = -126.f, mx1 = -126.f, mx2 = -126.f, mx3 = -126.f;

    const ulonglong2* skv2 = (const ulonglong2*)skv;

    #pragma unroll 1
    for (int si = 0; si < 2; si++) {
        if (si) __syncthreads();
        {   // stage interleaved kv page for s = sg*2+si (swizzled)
            const float4* src = (const float4*)(g_kv +
                ((((size_t)b*NHh + head)*TT + (sg*2 + si))*HWp)*16);
            #pragma unroll
            for (int r = 0; r < 16; r++) {
                int g = tid + r*112;
                skv[g ^ ((g >> 3) & 7)] = src[g];
            }
        }
        __syncthreads();

        #pragma unroll 1
        for (int oy = -3; oy <= 3; oy++) {
            int yy = y + oy*dil;
            if ((unsigned)yy < (unsigned)HH) {
                int rb = yy * WW;
                #pragma unroll 2
                for (int i = 0; i < 7; i++) {
                    int xx = xq + (i - 3)*dil;
                    bool vx = (unsigned)xx < (unsigned)WW;
                    int sp  = vx ? (rb + xx) : HWp;       // HWp -> zero zone
                    float bv = vx ? -32.f : -126.f;

                    int gb = 4*sp;
                    int m  = (sp >> 1) & 7;
                    ulonglong2 kA = skv2[(gb    ) ^ m];
                    ulonglong2 kB = skv2[(gb + 1) ^ m];
                    ulonglong2 vA = skv2[(gb + 2) ^ m];
                    ulonglong2 vB = skv2[(gb + 3) ^ m];

                    ull d0 = mul2(qp[0][0], kA.x);
                    ull d1 = mul2(qp[1][0], kA.x);
                    ull d2 = mul2(qp[2][0], kA.x);
                    ull d3 = mul2(qp[3][0], kA.x);
                    d0 = fma2(qp[0][1], kA.y, d0); d1 = fma2(qp[1][1], kA.y, d1);
                    d2 = fma2(qp[2][1], kA.y, d2); d3 = fma2(qp[3][1], kA.y, d3);
                    d0 = fma2(qp[0][2], kB.x, d0); d1 = fma2(qp[1][2], kB.x, d1);
                    d2 = fma2(qp[2][2], kB.x, d2); d3 = fma2(qp[3][2], kB.x, d3);
                    d0 = fma2(qp[0][3], kB.y, d0); d1 = fma2(qp[1][3], kB.y, d1);
                    d2 = fma2(qp[2][3], kB.y, d2); d3 = fma2(qp[3][3], kB.y, d3);

                    // horizontal add, results packed over t-pairs
                    float d0l,d0h,d1l,d1h,d2l,d2h,d3l,d3h;
                    unpack2(d0,d0l,d0h); unpack2(d1,d1l,d1h);
                    unpack2(d2,d2l,d2h); unpack2(d3,d3l,d3h);
                    ull s01 = add2(pack2(d0l,d1l), pack2(d0h,d1h));  // (sc0,sc1)
                    ull s23 = add2(pack2(d2l,d3l), pack2(d2h,d3h));  // (sc2,sc3)

                    ull w01 = mul2(s01, INV2);
                    ull w23 = mul2(s23, INV2);
                    float w0,w1,w2,w3;
                    unpack2(w01,w0,w1); unpack2(w23,w2,w3);
                    ull wp0 = pack2(w0,w0), wp1 = pack2(w1,w1);
                    ull wp2 = pack2(w2,w2), wp3 = pack2(w3,w3);

                    tout[0][0] = fma2(wp0, vA.x, tout[0][0]);
                    tout[1][0] = fma2(wp1, vA.x, tout[1][0]);
                    tout[2][0] = fma2(wp2, vA.x, tout[2][0]);
                    tout[3][0] = fma2(wp3, vA.x, tout[3][0]);
                    tout[0][1] = fma2(wp0, vA.y, tout[0][1]);
                    tout[1][1] = fma2(wp1, vA.y, tout[1][1]);
                    tout[2][1] = fma2(wp2, vA.y, tout[2][1]);
                    tout[3][1] = fma2(wp3, vA.y, tout[3][1]);
                    tout[0][2] = fma2(wp0, vB.x, tout[0][2]);
                    tout[1][2] = fma2(wp1, vB.x, tout[1][2]);
                    tout[2][2] = fma2(wp2, vB.x, tout[2][2]);
                    tout[3][2] = fma2(wp3, vB.x, tout[3][2]);
                    tout[0][3] = fma2(wp0, vB.y, tout[0][3]);
                    tout[1][3] = fma2(wp1, vB.y, tout[1][3]);
                    tout[2][3] = fma2(wp2, vB.y, tout[2][3]);
                    tout[3][3] = fma2(wp3, vB.y, tout[3][3]);

                    ull bv2 = pack2(bv, bv);
                    ull a01 = fma2(s01, S2_2, bv2);
                    ull a23 = fma2(s23, S2_2, bv2);
                    float a0,a1,a2,a3;
                    unpack2(a01,a0,a1); unpack2(a23,a2,a3);
                    mx0 = fmaxf(mx0,a0); mx1 = fmaxf(mx1,a1);
                    mx2 = fmaxf(mx2,a2); mx3 = fmaxf(mx3,a3);
                    summ01 = add2(summ01, exp2x2(a01));
                    summ23 = add2(summ23, exp2x2(a23));
                }
            }
        }
    }

    // coalesced partial stores: [ss][bt][h*8+c][p], [ss][bt][h][p]
    float su[4], mxv[4] = {mx0, mx1, mx2, mx3};
    unpack2(summ01, su[0], su[1]);
    unpack2(summ23, su[2], su[3]);
    #pragma unroll
    for (int t = 0; t < 4; t++) {
        int bt = b*TT + t0 + t;
        float e[8];
        #pragma unroll
        for (int j = 0; j < 4; j++) unpack2(tout[t][j], e[2*j], e[2*j+1]);
        float* tb = g_tout + (((size_t)(sg*(BB*TT) + bt))*CC + head*DKk)*HWp + p;
        #pragma unroll
        for (int c = 0; c < 8; c++) tb[c*HWp] = e[c];
        size_t mi = (((size_t)(sg*(BB*TT) + bt))*NHh + head)*HWp + p;
        g_sum[mi] = su[t];
        g_mx[mi]  = mxv[t];
    }
}

// ---------------- K4: combine + M_S + output projection ----------------
__global__ __launch_bounds__(128)
void k_out(const float* __restrict__ Wo, float* __restrict__ out) {
    __shared__ float swo[1024];
    int tid = threadIdx.x;
    for (int i = tid; i < 1024; i += 128) swo[i] = Wo[i];
    __syncthreads();

    int gi = blockIdx.x * 128 + tid;              // [0, 57344)
    int p  = gi % HWp;
    int r  = gi / HWp;                            // [0, 128)
    int bt = r >> 1;
    int oh = (r & 1) * 16;

    float tc[CC];
    #pragma unroll
    for (int hc = 0; hc < CC; hc++) {
        float acc = 0.f;
        #pragma unroll
        for (int ssi = 0; ssi < SGn; ssi++)
            acc += g_tout[(((size_t)(ssi*(BB*TT) + bt))*CC + hc)*HWp + p];
        tc[hc] = acc;
    }
    ull tc2[16];
    #pragma unroll
    for (int j = 0; j < 16; j++) tc2[j] = pack2(tc[2*j], tc[2*j+1]);

    float MS = 0.f;
    #pragma unroll
    for (int h = 0; h < NHh; h++) {
        float s = 0.f, m = -1e30f;
        #pragma unroll
        for (int ssi = 0; ssi < SGn; ssi++) {
            size_t mi = (((size_t)(ssi*(BB*TT) + bt))*NHh + h)*HWp + p;
            s += g_sum[mi];
            m  = fmaxf(m, g_mx[mi]);
        }
        MS = fmaxf(MS, __fdividef(exp2_fast(m), s));
    }

    float* ob = out + (size_t)bt * CC * HWp + p;
    #pragma unroll
    for (int o = oh; o < oh + 16; o++) {
        const ull* wp = (const ull*)&swo[o*CC];
        ull acc = mul2(tc2[0], wp[0]);
        #pragma unroll
        for (int j = 1; j < 16; j++) acc = fma2(tc2[j], wp[j], acc);
        float l, h; unpack2(acc, l, h);
        ob[o*HWp] = (l + h) * MS;
    }
}

// ---------------- launcher ----------------
extern "C" void kernel_launch(void* const* d_in, const int* in_sizes, int n_in,
                              void* d_out, int out_size) {
    const float* first = (const float*)d_in[0];
    const float* x     = (const float*)d_in[1];
    const float* Wq    = (const float*)d_in[2];
    const float* Wk    = (const float*)d_in[3];
    const float* Wv    = (const float*)d_in[4];
    const float* Wo    = (const float*)d_in[5];
    const float* lng   = (const float*)d_in[6];
    const float* lnb   = (const float*)d_in[7];
    float* out = (float*)d_out;

    k_proj<<<224, 128>>>(first, x, Wq, Wk, Wv);
    k_ln<<<BB*TT*NHh, 128>>>(lng, lnb);
    k_attn<<<1024, 112>>>();
    k_out<<<448, 128>>>(Wo, out);
}

// round 5
// speedup vs baseline: 1.2255x; 1.0250x over previous
#include <cuda_runtime.h>

typedef unsigned long long ull;

// ---------------- problem constants ----------------
#define BB   8
#define TT   8
#define CC   32
#define HH   16
#define WW   28
#define HWp  448
#define NHh  4
#define DKk  8

// ---------------- device scratch ----------------
__device__ __align__(16) float g_q   [BB*TT*CC*HWp];          // [bt][o][p]
__device__ __align__(16) float g_kv  [BB*NHh*TT*HWp*16];      // [b][h][s][p][k0..7 v0..7]
__device__ __align__(16) float g_tout[BB*TT*CC*HWp];          // combined [bt][h*8+c][p]
__device__ __align__(16) float g_sum [BB*TT*NHh*HWp];         // combined [bt][h][p]
__device__ __align__(16) unsigned g_mx[BB*TT*NHh*HWp];        // monotonic-mapped max

#define TOUTN (BB*TT*CC*HWp)
#define SUMN  (BB*TT*NHh*HWp)

// ---------------- packed f32x2 helpers ----------------
__device__ __forceinline__ ull pack2(float lo, float hi){ ull r; asm("mov.b64 %0,{%1,%2};":"=l"(r):"f"(lo),"f"(hi)); return r; }
__device__ __forceinline__ void unpack2(ull v, float& lo, float& hi){ asm("mov.b64 {%0,%1},%2;":"=f"(lo),"=f"(hi):"l"(v)); }
__device__ __forceinline__ ull pack2i(int lo, int hi){ ull r; asm("mov.b64 %0,{%1,%2};":"=l"(r):"r"(lo),"r"(hi)); return r; }
__device__ __forceinline__ void unpack2i(ull v, int& lo, int& hi){ asm("mov.b64 {%0,%1},%2;":"=r"(lo),"=r"(hi):"l"(v)); }
__device__ __forceinline__ ull fma2(ull a, ull b, ull c){ ull d; asm("fma.rn.f32x2 %0,%1,%2,%3;":"=l"(d):"l"(a),"l"(b),"l"(c)); return d; }
__device__ __forceinline__ ull add2(ull a, ull b){ ull d; asm("add.rn.f32x2 %0,%1,%2;":"=l"(d):"l"(a),"l"(b)); return d; }
__device__ __forceinline__ ull mul2(ull a, ull b){ ull d; asm("mul.rn.f32x2 %0,%1,%2;":"=l"(d):"l"(a),"l"(b)); return d; }

__device__ __forceinline__ float exp2_fast(float x) {
    float z = __fadd_rn(x, 12582912.0f);
    float n = __fadd_rn(z, -12582912.0f);
    float f = x - n;
    int   sb = __float_as_int(z) * 8388608 + 0x3F800000;
    float p = fmaf(fmaf(fmaf(fmaf(0.0096181291f, f, 0.055504109f),
                             f, 0.24022651f), f, 0.69314718f), f, 1.0f);
    return p * __int_as_float(sb);
}

__device__ __forceinline__ ull exp2x2(ull x) {
    const ull C2  = pack2( 12582912.0f,  12582912.0f);
    const ull nC2 = pack2(-12582912.0f, -12582912.0f);
    const ull n1  = pack2(-1.0f, -1.0f);
    const ull c4  = pack2(0.0096181291f, 0.0096181291f);
    const ull c3  = pack2(0.055504109f,  0.055504109f);
    const ull c2  = pack2(0.24022651f,   0.24022651f);
    const ull c1  = pack2(0.69314718f,   0.69314718f);
    const ull one = pack2(1.0f, 1.0f);
    ull z = add2(x, C2);
    ull n = add2(z, nC2);
    ull f = fma2(n, n1, x);
    ull p = fma2(fma2(fma2(fma2(c4, f, c3), f, c2), f, c1), f, one);
    int zl, zh; unpack2i(z, zl, zh);
    int sl = zl * 8388608 + 0x3F800000;
    int sh = zh * 8388608 + 0x3F800000;
    return mul2(p, pack2i(sl, sh));
}

// monotonic float->uint map (order-preserving for all finite floats)
__device__ __forceinline__ unsigned fmap(float f) {
    unsigned u = __float_as_uint(f);
    return (u & 0x80000000u) ? ~u : (u | 0x80000000u);
}
__device__ __forceinline__ float funmap(unsigned m) {
    return (m & 0x80000000u) ? __uint_as_float(m ^ 0x80000000u)
                             : __uint_as_float(~m);
}

// ---------------- K0: init combine buffers ----------------
__global__ __launch_bounds__(256)
void k_init() {
    int i = blockIdx.x * 256 + threadIdx.x;
    int stride = gridDim.x * 256;
    for (int j = i; j < TOUTN/4; j += stride) ((float4*)g_tout)[j] = make_float4(0.f,0.f,0.f,0.f);
    for (int j = i; j < SUMN/4;  j += stride) ((float4*)g_sum)[j]  = make_float4(0.f,0.f,0.f,0.f);
    for (int j = i; j < SUMN/4;  j += stride) ((uint4*)g_mx)[j]    = make_uint4(0u,0u,0u,0u);
}

// ---------------- K1: Q/K/V projections ----------------
__global__ __launch_bounds__(128)
void k_proj(const float* __restrict__ first, const float* __restrict__ x,
            const float* __restrict__ Wq, const float* __restrict__ Wk,
            const float* __restrict__ Wv) {
    __shared__ float swq[1024], swk[1024], swv[1024];
    int tid = threadIdx.x;
    for (int i = tid; i < 1024; i += 128) { swq[i]=Wq[i]; swk[i]=Wk[i]; swv[i]=Wv[i]; }
    __syncthreads();

    int gi = blockIdx.x * 128 + tid;
    int p  = gi % HWp;
    int bt = gi / HWp;
    int b  = bt >> 3, t = bt & 7;

    const float* fb = first + (size_t)bt * CC * HWp + p;
    const float* xb = x     + (size_t)bt * CC * HWp + p;
    ull fp[16], xp[16];
    #pragma unroll
    for (int j = 0; j < 16; j++) {
        fp[j] = pack2(fb[(2*j)*HWp], fb[(2*j+1)*HWp]);
        xp[j] = pack2(xb[(2*j)*HWp], xb[(2*j+1)*HWp]);
    }

    #pragma unroll
    for (int h = 0; h < NHh; h++) {
        float kr[8], vr[8];
        #pragma unroll
        for (int c8 = 0; c8 < 8; c8++) {
            int o = h*8 + c8;
            const ull* wq = (const ull*)&swq[o*CC];
            const ull* wk = (const ull*)&swk[o*CC];
            const ull* wv = (const ull*)&swv[o*CC];
            ull aq = mul2(fp[0], wq[0]);
            ull ak = mul2(xp[0], wk[0]);
            ull av = mul2(xp[0], wv[0]);
            #pragma unroll
            for (int j = 1; j < 16; j++) {
                aq = fma2(fp[j], wq[j], aq);
                ak = fma2(xp[j], wk[j], ak);
                av = fma2(xp[j], wv[j], av);
            }
            float l, hh;
            unpack2(aq, l, hh);
            g_q[((size_t)bt*CC + o)*HWp + p] = l + hh;
            unpack2(ak, l, hh); kr[c8] = l + hh;
            unpack2(av, l, hh); vr[c8] = l + hh;
        }
        float* dst = g_kv + ((((size_t)b*NHh + h)*TT + t)*HWp + p)*16;
        *(float4*)(dst)      = make_float4(kr[0], kr[1], kr[2], kr[3]);
        *(float4*)(dst + 4)  = make_float4(kr[4], kr[5], kr[6], kr[7]);
        *(float4*)(dst + 8)  = make_float4(vr[0], vr[1], vr[2], vr[3]);
        *(float4*)(dst + 12) = make_float4(vr[4], vr[5], vr[6], vr[7]);
    }
}

// ---------------- K2: per-(b,t,head) LayerNorm of q ----------------
__global__ __launch_bounds__(128)
void k_ln(const float* __restrict__ gamma, const float* __restrict__ beta) {
    const int N = DKk * HWp;                      // 3584
    float* base = g_q + (size_t)blockIdx.x * N;
    int tid = threadIdx.x;

    float vals[28];
    float s = 0.f, sq = 0.f;
    #pragma unroll
    for (int i = 0; i < 28; i++) {
        float v = base[tid + i*128];
        vals[i] = v; s += v; sq = fmaf(v, v, sq);
    }
    #pragma unroll
    for (int o = 16; o > 0; o >>= 1) {
        s  += __shfl_xor_sync(0xFFFFFFFFu, s,  o);
        sq += __shfl_xor_sync(0xFFFFFFFFu, sq, o);
    }
    __shared__ float shs[4], shq[4];
    if ((tid & 31) == 0) { shs[tid>>5] = s; shq[tid>>5] = sq; }
    __syncthreads();
    s  = shs[0]+shs[1]+shs[2]+shs[3];
    sq = shq[0]+shq[1]+shq[2]+shq[3];

    float mu   = s * (1.0f/3584.0f);
    float var  = fmaf(-mu, mu, sq * (1.0f/3584.0f));
    float rstd = rsqrtf(var + 1e-5f);
    #pragma unroll
    for (int i = 0; i < 28; i++) {
        int idx = tid + i*128;
        base[idx] = fmaf((vals[i]-mu)*rstd, gamma[idx], beta[idx]);
    }
}

// ---------------- K3: dilated local attention, t-group 8, RED combine ----------------
// grid = 1024: bid = [b(3)][s(3)][head(2)][ys(2)]; head at bits 2:3 so
// co-resident blocks (stride 148) rotate head -> per-SM dilation mix.
__global__ __launch_bounds__(112, 3)
void k_attn() {
    int bid  = blockIdx.x;
    int ys   = bid & 3;
    int head = (bid >> 2) & 3;
    int s    = (bid >> 4) & 7;
    int b    = bid >> 7;
    const int dil = 2*head + 1;

    __shared__ float4 skv[1800];                  // 1792 data + 4 zero + pad

    int tid = threadIdx.x;
    int row = tid / WW;                           // 0..3
    int xq  = tid - row*WW;
    int y   = ys*4 + row;
    int p   = y*WW + xq;

    if (tid < 4) skv[1792 + tid] = make_float4(0.f, 0.f, 0.f, 0.f);
    {   // stage interleaved kv page for this s (swizzled)
        const float4* src = (const float4*)(g_kv +
            ((((size_t)b*NHh + head)*TT + s)*HWp)*16);
        #pragma unroll
        for (int r = 0; r < 16; r++) {
            int g = tid + r*112;
            skv[g ^ ((g >> 3) & 7)] = src[g];
        }
    }

    const float INV = 0.35355339059327373f;                 // 1/sqrt(C/NH)
    const float S2C = 0.35355339059327373f * 1.4426950408889634f;
    const ull INV2 = pack2(INV, INV);
    const ull S2_2 = pack2(S2C, S2C);

    // q: 8 timesteps x 8 channels as c-pairs
    ull qp[8][4];
    #pragma unroll
    for (int t = 0; t < 8; t++) {
        const float* qb = g_q + ((size_t)(b*TT + t)*CC + head*DKk)*HWp + p;
        #pragma unroll
        for (int j = 0; j < 4; j++)
            qp[t][j] = pack2(qb[(2*j)*HWp], qb[(2*j+1)*HWp]);
    }

    ull tout[8][4];
    #pragma unroll
    for (int t = 0; t < 8; t++)
        #pragma unroll
        for (int j = 0; j < 4; j++) tout[t][j] = pack2(0.f, 0.f);
    ull summ[4];
    #pragma unroll
    for (int j = 0; j < 4; j++) summ[j] = pack2(0.f, 0.f);
    float mx[8];
    #pragma unroll
    for (int t = 0; t < 8; t++) mx[t] = -126.f;

    const ulonglong2* skv2 = (const ulonglong2*)skv;
    __syncthreads();

    #pragma unroll 1
    for (int oy = -3; oy <= 3; oy++) {
        int yy = y + oy*dil;
        if ((unsigned)yy < (unsigned)HH) {
            int rb = yy * WW;
            #pragma unroll 1
            for (int i = 0; i < 7; i++) {
                int xx = xq + (i - 3)*dil;
                bool vx = (unsigned)xx < (unsigned)WW;
                int sp  = vx ? (rb + xx) : HWp;   // HWp -> zero zone
                float bv = vx ? -32.f : -126.f;

                int gb = 4*sp;
                int m  = (sp >> 1) & 7;
                ulonglong2 kA = skv2[(gb    ) ^ m];
                ulonglong2 kB = skv2[(gb + 1) ^ m];
                ulonglong2 vA = skv2[(gb + 2) ^ m];
                ulonglong2 vB = skv2[(gb + 3) ^ m];

                ull d[8];
                #pragma unroll
                for (int t = 0; t < 8; t++) {
                    ull acc = mul2(qp[t][0], kA.x);
                    acc = fma2(qp[t][1], kA.y, acc);
                    acc = fma2(qp[t][2], kB.x, acc);
                    acc = fma2(qp[t][3], kB.y, acc);
                    d[t] = acc;
                }

                // horizontal add into t-pairs
                ull sc[4];
                #pragma unroll
                for (int tp = 0; tp < 4; tp++) {
                    float l0,h0,l1,h1;
                    unpack2(d[2*tp],   l0, h0);
                    unpack2(d[2*tp+1], l1, h1);
                    sc[tp] = add2(pack2(l0, l1), pack2(h0, h1));
                }

                ull bv2 = pack2(bv, bv);
                #pragma unroll
                for (int tp = 0; tp < 4; tp++) {
                    ull w2 = mul2(sc[tp], INV2);
                    float w0, w1; unpack2(w2, w0, w1);
                    ull wp0 = pack2(w0, w0), wp1 = pack2(w1, w1);
                    tout[2*tp][0]   = fma2(wp0, vA.x, tout[2*tp][0]);
                    tout[2*tp][1]   = fma2(wp0, vA.y, tout[2*tp][1]);
                    tout[2*tp][2]   = fma2(wp0, vB.x, tout[2*tp][2]);
                    tout[2*tp][3]   = fma2(wp0, vB.y, tout[2*tp][3]);
                    tout[2*tp+1][0] = fma2(wp1, vA.x, tout[2*tp+1][0]);
                    tout[2*tp+1][1] = fma2(wp1, vA.y, tout[2*tp+1][1]);
                    tout[2*tp+1][2] = fma2(wp1, vB.x, tout[2*tp+1][2]);
                    tout[2*tp+1][3] = fma2(wp1, vB.y, tout[2*tp+1][3]);

                    ull a2 = fma2(sc[tp], S2_2, bv2);
                    float a0, a1; unpack2(a2, a0, a1);
                    mx[2*tp]   = fmaxf(mx[2*tp],   a0);
                    mx[2*tp+1] = fmaxf(mx[2*tp+1], a1);
                    summ[tp] = add2(summ[tp], exp2x2(a2));
                }
            }
        }
    }

    // RED-combine into global buffers
    #pragma unroll
    for (int t = 0; t < 8; t++) {
        int bt = b*TT + t;
        float e[8];
        #pragma unroll
        for (int j = 0; j < 4; j++) unpack2(tout[t][j], e[2*j], e[2*j+1]);
        float* tb = g_tout + ((size_t)bt*CC + head*DKk)*HWp + p;
        #pragma unroll
        for (int c = 0; c < 8; c++) atomicAdd(tb + c*HWp, e[c]);
        size_t mi = ((size_t)bt*NHh + head)*HWp + p;
        float sl, sh; unpack2(summ[t>>1], sl, sh);
        atomicAdd(g_sum + mi, (t & 1) ? sh : sl);
        atomicMax(g_mx + mi, fmap(mx[t]));
    }
}

// ---------------- K4: M_S + output projection ----------------
__global__ __launch_bounds__(128)
void k_out(const float* __restrict__ Wo, float* __restrict__ out) {
    __shared__ float swo[1024];
    int tid = threadIdx.x;
    for (int i = tid; i < 1024; i += 128) swo[i] = Wo[i];
    __syncthreads();

    int gi = blockIdx.x * 128 + tid;              // [0, 57344)
    int p  = gi % HWp;
    int r  = gi / HWp;
    int bt = r >> 1;
    int oh = (r & 1) * 16;

    ull tc2[16];
    #pragma unroll
    for (int j = 0; j < 16; j++) {
        float a = g_tout[((size_t)bt*CC + 2*j    )*HWp + p];
        float b = g_tout[((size_t)bt*CC + 2*j + 1)*HWp + p];
        tc2[j] = pack2(a, b);
    }

    float MS = 0.f;
    #pragma unroll
    for (int h = 0; h < NHh; h++) {
        size_t mi = ((size_t)bt*NHh + h)*HWp + p;
        float s = g_sum[mi];
        float m = funmap(g_mx[mi]);
        MS = fmaxf(MS, __fdividef(exp2_fast(m), s));
    }

    float* ob = out + (size_t)bt * CC * HWp + p;
    #pragma unroll
    for (int o = oh; o < oh + 16; o++) {
        const ull* wp = (const ull*)&swo[o*CC];
        ull acc = mul2(tc2[0], wp[0]);
        #pragma unroll
        for (int j = 1; j < 16; j++) acc = fma2(tc2[j], wp[j], acc);
        float l, h; unpack2(acc, l, h);
        ob[o*HWp] = (l + h) * MS;
    }
}

// ---------------- launcher ----------------
extern "C" void kernel_launch(void* const* d_in, const int* in_sizes, int n_in,
                              void* d_out, int out_size) {
    const float* first = (const float*)d_in[0];
    const float* x     = (const float*)d_in[1];
    const float* Wq    = (const float*)d_in[2];
    const float* Wk    = (const float*)d_in[3];
    const float* Wv    = (const float*)d_in[4];
    const float* Wo    = (const float*)d_in[5];
    const float* lng   = (const float*)d_in[6];
    const float* lnb   = (const float*)d_in[7];
    float* out = (float*)d_out;

    k_init<<<296, 256>>>();
    k_proj<<<224, 128>>>(first, x, Wq, Wk, Wv);
    k_ln<<<BB*TT*NHh, 128>>>(lng, lnb);
    k_attn<<<1024, 112>>>();
    k_out<<<448, 128>>>(Wo, out);
}

// round 6
// speedup vs baseline: 1.3369x; 1.0909x over previous
#include <cuda_runtime.h>

typedef unsigned long long ull;

// ---------------- problem constants ----------------
#define BB   8
#define TT   8
#define CC   32
#define HH   16
#define WW   28
#define HWp  448
#define NHh  4
#define DKk  8

// ---------------- device scratch ----------------
__device__ __align__(16) float g_q   [BB*TT*CC*HWp];          // [bt][o][p]
__device__ __align__(16) float g_kv  [BB*NHh*TT*HWp*16];      // [b][h][s][p][k0..7 v0..7]
__device__ __align__(16) float g_tout[BB*TT*CC*HWp];          // combined [bt][h*8+c][p]
__device__ __align__(16) float g_sum [BB*TT*NHh*HWp];         // combined [bt][h][p]
__device__ __align__(16) unsigned g_mx[BB*TT*NHh*HWp];        // monotonic-mapped max

#define TOUTN (BB*TT*CC*HWp)
#define SUMN  (BB*TT*NHh*HWp)

// ---------------- packed f32x2 helpers ----------------
__device__ __forceinline__ ull pack2(float lo, float hi){ ull r; asm("mov.b64 %0,{%1,%2};":"=l"(r):"f"(lo),"f"(hi)); return r; }
__device__ __forceinline__ void unpack2(ull v, float& lo, float& hi){ asm("mov.b64 {%0,%1},%2;":"=f"(lo),"=f"(hi):"l"(v)); }
__device__ __forceinline__ ull pack2i(int lo, int hi){ ull r; asm("mov.b64 %0,{%1,%2};":"=l"(r):"r"(lo),"r"(hi)); return r; }
__device__ __forceinline__ void unpack2i(ull v, int& lo, int& hi){ asm("mov.b64 {%0,%1},%2;":"=r"(lo),"=r"(hi):"l"(v)); }
__device__ __forceinline__ ull fma2(ull a, ull b, ull c){ ull d; asm("fma.rn.f32x2 %0,%1,%2,%3;":"=l"(d):"l"(a),"l"(b),"l"(c)); return d; }
__device__ __forceinline__ ull add2(ull a, ull b){ ull d; asm("add.rn.f32x2 %0,%1,%2;":"=l"(d):"l"(a),"l"(b)); return d; }
__device__ __forceinline__ ull mul2(ull a, ull b){ ull d; asm("mul.rn.f32x2 %0,%1,%2;":"=l"(d):"l"(a),"l"(b)); return d; }

__device__ __forceinline__ float exp2_fast(float x) {
    float z = __fadd_rn(x, 12582912.0f);
    float n = __fadd_rn(z, -12582912.0f);
    float f = x - n;
    int   sb = __float_as_int(z) * 8388608 + 0x3F800000;
    float p = fmaf(fmaf(fmaf(fmaf(0.0096181291f, f, 0.055504109f),
                             f, 0.24022651f), f, 0.69314718f), f, 1.0f);
    return p * __int_as_float(sb);
}

__device__ __forceinline__ ull exp2x2(ull x) {
    const ull C2  = pack2( 12582912.0f,  12582912.0f);
    const ull nC2 = pack2(-12582912.0f, -12582912.0f);
    const ull n1  = pack2(-1.0f, -1.0f);
    const ull c4  = pack2(0.0096181291f, 0.0096181291f);
    const ull c3  = pack2(0.055504109f,  0.055504109f);
    const ull c2  = pack2(0.24022651f,   0.24022651f);
    const ull c1  = pack2(0.69314718f,   0.69314718f);
    const ull one = pack2(1.0f, 1.0f);
    ull z = add2(x, C2);
    ull n = add2(z, nC2);
    ull f = fma2(n, n1, x);
    ull p = fma2(fma2(fma2(fma2(c4, f, c3), f, c2), f, c1), f, one);
    int zl, zh; unpack2i(z, zl, zh);
    int sl = zl * 8388608 + 0x3F800000;
    int sh = zh * 8388608 + 0x3F800000;
    return mul2(p, pack2i(sl, sh));
}

// monotonic float->uint map
__device__ __forceinline__ unsigned fmap(float f) {
    unsigned u = __float_as_uint(f);
    return (u & 0x80000000u) ? ~u : (u | 0x80000000u);
}
__device__ __forceinline__ float funmap(unsigned m) {
    return (m & 0x80000000u) ? __uint_as_float(m ^ 0x80000000u)
                             : __uint_as_float(~m);
}

// ---------------- K0: init combine buffers ----------------
__global__ __launch_bounds__(256)
void k_init() {
    int i = blockIdx.x * 256 + threadIdx.x;
    int stride = gridDim.x * 256;
    for (int j = i; j < TOUTN/4; j += stride) ((float4*)g_tout)[j] = make_float4(0.f,0.f,0.f,0.f);
    for (int j = i; j < SUMN/4;  j += stride) ((float4*)g_sum)[j]  = make_float4(0.f,0.f,0.f,0.f);
    for (int j = i; j < SUMN/4;  j += stride) ((uint4*)g_mx)[j]    = make_uint4(0u,0u,0u,0u);
}

// ---------------- K1: Q/K/V projections ----------------
__global__ __launch_bounds__(128)
void k_proj(const float* __restrict__ first, const float* __restrict__ x,
            const float* __restrict__ Wq, const float* __restrict__ Wk,
            const float* __restrict__ Wv) {
    __shared__ float swq[1024], swk[1024], swv[1024];
    int tid = threadIdx.x;
    for (int i = tid; i < 1024; i += 128) { swq[i]=Wq[i]; swk[i]=Wk[i]; swv[i]=Wv[i]; }
    __syncthreads();

    int gi = blockIdx.x * 128 + tid;
    int p  = gi % HWp;
    int bt = gi / HWp;
    int b  = bt >> 3, t = bt & 7;

    const float* fb = first + (size_t)bt * CC * HWp + p;
    const float* xb = x     + (size_t)bt * CC * HWp + p;
    ull fp[16], xp[16];
    #pragma unroll
    for (int j = 0; j < 16; j++) {
        fp[j] = pack2(fb[(2*j)*HWp], fb[(2*j+1)*HWp]);
        xp[j] = pack2(xb[(2*j)*HWp], xb[(2*j+1)*HWp]);
    }

    #pragma unroll
    for (int h = 0; h < NHh; h++) {
        float kr[8], vr[8];
        #pragma unroll
        for (int c8 = 0; c8 < 8; c8++) {
            int o = h*8 + c8;
            const ull* wq = (const ull*)&swq[o*CC];
            const ull* wk = (const ull*)&swk[o*CC];
            const ull* wv = (const ull*)&swv[o*CC];
            ull aq = mul2(fp[0], wq[0]);
            ull ak = mul2(xp[0], wk[0]);
            ull av = mul2(xp[0], wv[0]);
            #pragma unroll
            for (int j = 1; j < 16; j++) {
                aq = fma2(fp[j], wq[j], aq);
                ak = fma2(xp[j], wk[j], ak);
                av = fma2(xp[j], wv[j], av);
            }
            float l, hh;
            unpack2(aq, l, hh);
            g_q[((size_t)bt*CC + o)*HWp + p] = l + hh;
            unpack2(ak, l, hh); kr[c8] = l + hh;
            unpack2(av, l, hh); vr[c8] = l + hh;
        }
        float* dst = g_kv + ((((size_t)b*NHh + h)*TT + t)*HWp + p)*16;
        *(float4*)(dst)      = make_float4(kr[0], kr[1], kr[2], kr[3]);
        *(float4*)(dst + 4)  = make_float4(kr[4], kr[5], kr[6], kr[7]);
        *(float4*)(dst + 8)  = make_float4(vr[0], vr[1], vr[2], vr[3]);
        *(float4*)(dst + 12) = make_float4(vr[4], vr[5], vr[6], vr[7]);
    }
}

// ---------------- K2: per-(b,t,head) LayerNorm of q ----------------
__global__ __launch_bounds__(128)
void k_ln(const float* __restrict__ gamma, const float* __restrict__ beta) {
    const int N = DKk * HWp;                      // 3584
    float* base = g_q + (size_t)blockIdx.x * N;
    int tid = threadIdx.x;

    float vals[28];
    float s = 0.f, sq = 0.f;
    #pragma unroll
    for (int i = 0; i < 28; i++) {
        float v = base[tid + i*128];
        vals[i] = v; s += v; sq = fmaf(v, v, sq);
    }
    #pragma unroll
    for (int o = 16; o > 0; o >>= 1) {
        s  += __shfl_xor_sync(0xFFFFFFFFu, s,  o);
        sq += __shfl_xor_sync(0xFFFFFFFFu, sq, o);
    }
    __shared__ float shs[4], shq[4];
    if ((tid & 31) == 0) { shs[tid>>5] = s; shq[tid>>5] = sq; }
    __syncthreads();
    s  = shs[0]+shs[1]+shs[2]+shs[3];
    sq = shq[0]+shq[1]+shq[2]+shq[3];

    float mu   = s * (1.0f/3584.0f);
    float var  = fmaf(-mu, mu, sq * (1.0f/3584.0f));
    float rstd = rsqrtf(var + 1e-5f);
    #pragma unroll
    for (int i = 0; i < 28; i++) {
        int idx = tid + i*128;
        base[idx] = fmaf((vals[i]-mu)*rstd, gamma[idx], beta[idx]);
    }
}

// ---------------- K3: dilated local attention ----------------
// grid = 2048: bid = [b(3)][ts(1)][s(3)][head(2)][ys(2)]; head at bits 2:3
// mixes dilations across SMs. 128 threads = 4 warps; WARP = one y-row
// (lanes 28..31 idle) so the oy row-skip is warp-uniform.
__global__ __launch_bounds__(128, 4)
void k_attn() {
    int bid  = blockIdx.x;
    int ys   = bid & 3;
    int head = (bid >> 2) & 3;
    int s    = (bid >> 4) & 7;
    int ts   = (bid >> 7) & 1;
    int b    = bid >> 8;
    const int dil = 2*head + 1;

    __shared__ float4 skv[1800];                  // 1792 data + 4 zero + pad

    int tid  = threadIdx.x;
    int row  = tid >> 5;                          // warp id = row 0..3
    int lane = tid & 31;
    bool act = lane < WW;
    int xq   = lane;
    int y    = ys*4 + row;
    int p    = y*WW + (act ? xq : 0);
    int t0   = ts*4;

    if (tid < 4) skv[1792 + tid] = make_float4(0.f, 0.f, 0.f, 0.f);
    {   // stage interleaved kv page for this s (swizzled)
        const float4* src = (const float4*)(g_kv +
            ((((size_t)b*NHh + head)*TT + s)*HWp)*16);
        #pragma unroll
        for (int r = 0; r < 14; r++) {
            int g = tid + r*128;
            skv[g ^ ((g >> 3) & 7)] = src[g];
        }
    }

    const float INV = 0.35355339059327373f;                 // 1/sqrt(C/NH)
    const float S2C = 0.35355339059327373f * 1.4426950408889634f;
    const ull S2_2 = pack2(S2C, S2C);
    const ull BV_V = pack2(-32.f, -32.f);
    const ull BV_I = pack2(-126.f, -126.f);

    // q: 4 timesteps x 8 channels as c-pairs
    ull qp[4][4];
    #pragma unroll
    for (int t = 0; t < 4; t++) {
        const float* qb = g_q + ((size_t)(b*TT + t0 + t)*CC + head*DKk)*HWp + p;
        #pragma unroll
        for (int j = 0; j < 4; j++)
            qp[t][j] = pack2(qb[(2*j)*HWp], qb[(2*j+1)*HWp]);
    }

    ull tout[4][4];
    #pragma unroll
    for (int t = 0; t < 4; t++)
        #pragma unroll
        for (int j = 0; j < 4; j++) tout[t][j] = pack2(0.f, 0.f);
    ull summ[2] = { pack2(0.f, 0.f), pack2(0.f, 0.f) };
    float mx[4] = { -126.f, -126.f, -126.f, -126.f };

    const ulonglong2* skv2 = (const ulonglong2*)skv;
    __syncthreads();

    #pragma unroll 1
    for (int oy = -3; oy <= 3; oy++) {
        int yy = y + oy*dil;
        if ((unsigned)yy >= (unsigned)HH) continue;   // warp-uniform skip
        int rb = yy * WW;
        #pragma unroll 2
        for (int i = 0; i < 7; i++) {
            int xx = xq + (i - 3)*dil;
            bool vx = (unsigned)xx < (unsigned)WW;
            int sp  = vx ? (rb + xx) : HWp;           // HWp -> zero zone (k=v=0)
            ull bv2 = vx ? BV_V : BV_I;

            int gb = 4*sp;
            int m  = (sp >> 1) & 7;
            ulonglong2 kA = skv2[(gb    ) ^ m];
            ulonglong2 kB = skv2[(gb + 1) ^ m];
            ulonglong2 vA = skv2[(gb + 2) ^ m];
            ulonglong2 vB = skv2[(gb + 3) ^ m];

            ull d0 = mul2(qp[0][0], kA.x);
            ull d1 = mul2(qp[1][0], kA.x);
            ull d2 = mul2(qp[2][0], kA.x);
            ull d3 = mul2(qp[3][0], kA.x);
            d0 = fma2(qp[0][1], kA.y, d0); d1 = fma2(qp[1][1], kA.y, d1);
            d2 = fma2(qp[2][1], kA.y, d2); d3 = fma2(qp[3][1], kA.y, d3);
            d0 = fma2(qp[0][2], kB.x, d0); d1 = fma2(qp[1][2], kB.x, d1);
            d2 = fma2(qp[2][2], kB.x, d2); d3 = fma2(qp[3][2], kB.x, d3);
            d0 = fma2(qp[0][3], kB.y, d0); d1 = fma2(qp[1][3], kB.y, d1);
            d2 = fma2(qp[2][3], kB.y, d2); d3 = fma2(qp[3][3], kB.y, d3);

            // horizontal add -> raw scores packed over t-pairs
            float l0,h0,l1,h1,l2,h2,l3,h3;
            unpack2(d0,l0,h0); unpack2(d1,l1,h1);
            unpack2(d2,l2,h2); unpack2(d3,l3,h3);
            ull s01 = add2(pack2(l0,l1), pack2(h0,h1));
            ull s23 = add2(pack2(l2,l3), pack2(h2,h3));

            // tout accumulates RAW score * v (INV folded out of the loop);
            // zero-zone k=0 makes masked weights exactly 0.
            float w0,w1,w2,w3;
            unpack2(s01,w0,w1); unpack2(s23,w2,w3);
            ull wp0 = pack2(w0,w0), wp1 = pack2(w1,w1);
            ull wp2 = pack2(w2,w2), wp3 = pack2(w3,w3);
            tout[0][0] = fma2(wp0, vA.x, tout[0][0]);
            tout[1][0] = fma2(wp1, vA.x, tout[1][0]);
            tout[2][0] = fma2(wp2, vA.x, tout[2][0]);
            tout[3][0] = fma2(wp3, vA.x, tout[3][0]);
            tout[0][1] = fma2(wp0, vA.y, tout[0][1]);
            tout[1][1] = fma2(wp1, vA.y, tout[1][1]);
            tout[2][1] = fma2(wp2, vA.y, tout[2][1]);
            tout[3][1] = fma2(wp3, vA.y, tout[3][1]);
            tout[0][2] = fma2(wp0, vB.x, tout[0][2]);
            tout[1][2] = fma2(wp1, vB.x, tout[1][2]);
            tout[2][2] = fma2(wp2, vB.x, tout[2][2]);
            tout[3][2] = fma2(wp3, vB.x, tout[3][2]);
            tout[0][3] = fma2(wp0, vB.y, tout[0][3]);
            tout[1][3] = fma2(wp1, vB.y, tout[1][3]);
            tout[2][3] = fma2(wp2, vB.y, tout[2][3]);
            tout[3][3] = fma2(wp3, vB.y, tout[3][3]);

            ull a01 = fma2(s01, S2_2, bv2);
            ull a23 = fma2(s23, S2_2, bv2);
            float a0,a1,a2,a3;
            unpack2(a01,a0,a1); unpack2(a23,a2,a3);
            mx[0] = fmaxf(mx[0],a0); mx[1] = fmaxf(mx[1],a1);
            mx[2] = fmaxf(mx[2],a2); mx[3] = fmaxf(mx[3],a3);
            summ[0] = add2(summ[0], exp2x2(a01));
            summ[1] = add2(summ[1], exp2x2(a23));
        }
    }

    if (act) {
        float su[4];
        unpack2(summ[0], su[0], su[1]);
        unpack2(summ[1], su[2], su[3]);
        #pragma unroll
        for (int t = 0; t < 4; t++) {
            int bt = b*TT + t0 + t;
            float e[8];
            #pragma unroll
            for (int j = 0; j < 4; j++) unpack2(tout[t][j], e[2*j], e[2*j+1]);
            float* tb = g_tout + ((size_t)bt*CC + head*DKk)*HWp + p;
            #pragma unroll
            for (int c = 0; c < 8; c++) atomicAdd(tb + c*HWp, e[c] * INV);
            size_t mi = ((size_t)bt*NHh + head)*HWp + p;
            atomicAdd(g_sum + mi, su[t]);
            atomicMax(g_mx + mi, fmap(mx[t]));
        }
    }
}

// ---------------- K4: M_S + output projection ----------------
__global__ __launch_bounds__(128)
void k_out(const float* __restrict__ Wo, float* __restrict__ out) {
    __shared__ float swo[1024];
    int tid = threadIdx.x;
    for (int i = tid; i < 1024; i += 128) swo[i] = Wo[i];
    __syncthreads();

    int gi = blockIdx.x * 128 + tid;              // [0, 57344)
    int p  = gi % HWp;
    int r  = gi / HWp;
    int bt = r >> 1;
    int oh = (r & 1) * 16;

    ull tc2[16];
    #pragma unroll
    for (int j = 0; j < 16; j++) {
        float a = g_tout[((size_t)bt*CC + 2*j    )*HWp + p];
        float b = g_tout[((size_t)bt*CC + 2*j + 1)*HWp + p];
        tc2[j] = pack2(a, b);
    }

    float MS = 0.f;
    #pragma unroll
    for (int h = 0; h < NHh; h++) {
        size_t mi = ((size_t)bt*NHh + h)*HWp + p;
        float s = g_sum[mi];
        float m = funmap(g_mx[mi]);
        MS = fmaxf(MS, __fdividef(exp2_fast(m), s));
    }

    float* ob = out + (size_t)bt * CC * HWp + p;
    #pragma unroll
    for (int o = oh; o < oh + 16; o++) {
        const ull* wp = (const ull*)&swo[o*CC];
        ull acc = mul2(tc2[0], wp[0]);
        #pragma unroll
        for (int j = 1; j < 16; j++) acc = fma2(tc2[j], wp[j], acc);
        float l, h; unpack2(acc, l, h);
        ob[o*HWp] = (l + h) * MS;
    }
}

// ---------------- launcher ----------------
extern "C" void kernel_launch(void* const* d_in, const int* in_sizes, int n_in,
                              void* d_out, int out_size) {
    const float* first = (const float*)d_in[0];
    const float* x     = (const float*)d_in[1];
    const float* Wq    = (const float*)d_in[2];
    const float* Wk    = (const float*)d_in[3];
    const float* Wv    = (const float*)d_in[4];
    const float* Wo    = (const float*)d_in[5];
    const float* lng   = (const float*)d_in[6];
    const float* lnb   = (const float*)d_in[7];
    float* out = (float*)d_out;

    k_init<<<296, 256>>>();
    k_proj<<<224, 128>>>(first, x, Wq, Wk, Wv);
    k_ln<<<BB*TT*NHh, 128>>>(lng, lnb);
    k_attn<<<2048, 128>>>();
    k_out<<<448, 128>>>(Wo, out);
}

// round 7
// speedup vs baseline: 1.4452x; 1.0810x over previous
#include <cuda_runtime.h>

typedef unsigned long long ull;

// ---------------- problem constants ----------------
#define BB   8
#define TT   8
#define CC   32
#define HH   16
#define WW   28
#define HWp  448
#define NHh  4
#define DKk  8
#define PLN  449               // smem plane stride in 16B granules (448 + zero slot)

// ---------------- device scratch ----------------
__device__ __align__(16) float g_q   [BB*TT*CC*HWp];          // [bt][o][p]
// kv plane-major: [b][h][s][plane(6)][448] float4
//   planes 0..3: (k2j,k2j,k2j+1,k2j+1) ; planes 4..5: (v0..v3),(v4..v7)
__device__ __align__(16) float g_kv  [BB*NHh*TT*6*HWp*4];
__device__ __align__(16) float g_tout[BB*TT*CC*HWp];          // combined [bt][h*8+c][p]
__device__ __align__(16) float g_sum [BB*TT*NHh*HWp];         // combined [bt][h][p]
__device__ __align__(16) unsigned g_mx[BB*TT*NHh*HWp];        // monotonic-mapped max

#define TOUTN (BB*TT*CC*HWp)
#define SUMN  (BB*TT*NHh*HWp)

// ---------------- packed f32x2 helpers ----------------
__device__ __forceinline__ ull pack2(float lo, float hi){ ull r; asm("mov.b64 %0,{%1,%2};":"=l"(r):"f"(lo),"f"(hi)); return r; }
__device__ __forceinline__ void unpack2(ull v, float& lo, float& hi){ asm("mov.b64 {%0,%1},%2;":"=f"(lo),"=f"(hi):"l"(v)); }
__device__ __forceinline__ ull fma2(ull a, ull b, ull c){ ull d; asm("fma.rn.f32x2 %0,%1,%2,%3;":"=l"(d):"l"(a),"l"(b),"l"(c)); return d; }
__device__ __forceinline__ ull add2(ull a, ull b){ ull d; asm("add.rn.f32x2 %0,%1,%2;":"=l"(d):"l"(a),"l"(b)); return d; }
__device__ __forceinline__ ull mul2(ull a, ull b){ ull d; asm("mul.rn.f32x2 %0,%1,%2;":"=l"(d):"l"(a),"l"(b)); return d; }
__device__ __forceinline__ float ex2f(float x){ float y; asm("ex2.approx.f32 %0,%1;":"=f"(y):"f"(x)); return y; }

__device__ __forceinline__ float exp2_fast(float x) {   // k_out only
    float z = __fadd_rn(x, 12582912.0f);
    float n = __fadd_rn(z, -12582912.0f);
    float f = x - n;
    int   sb = __float_as_int(z) * 8388608 + 0x3F800000;
    float p = fmaf(fmaf(fmaf(fmaf(0.0096181291f, f, 0.055504109f),
                             f, 0.24022651f), f, 0.69314718f), f, 1.0f);
    return p * __int_as_float(sb);
}

// monotonic float->uint map
__device__ __forceinline__ unsigned fmap(float f) {
    unsigned u = __float_as_uint(f);
    return (u & 0x80000000u) ? ~u : (u | 0x80000000u);
}
__device__ __forceinline__ float funmap(unsigned m) {
    return (m & 0x80000000u) ? __uint_as_float(m ^ 0x80000000u)
                             : __uint_as_float(~m);
}

// ---------------- K0: init combine buffers ----------------
__global__ __launch_bounds__(256)
void k_init() {
    int i = blockIdx.x * 256 + threadIdx.x;
    int stride = gridDim.x * 256;
    for (int j = i; j < TOUTN/4; j += stride) ((float4*)g_tout)[j] = make_float4(0.f,0.f,0.f,0.f);
    for (int j = i; j < SUMN/4;  j += stride) ((float4*)g_sum)[j]  = make_float4(0.f,0.f,0.f,0.f);
    for (int j = i; j < SUMN/4;  j += stride) ((uint4*)g_mx)[j]    = make_uint4(0u,0u,0u,0u);
}

// ---------------- K1: Q/K/V projections ----------------
__global__ __launch_bounds__(128)
void k_proj(const float* __restrict__ first, const float* __restrict__ x,
            const float* __restrict__ Wq, const float* __restrict__ Wk,
            const float* __restrict__ Wv) {
    __shared__ float swq[1024], swk[1024], swv[1024];
    int tid = threadIdx.x;
    for (int i = tid; i < 1024; i += 128) { swq[i]=Wq[i]; swk[i]=Wk[i]; swv[i]=Wv[i]; }
    __syncthreads();

    int gi = blockIdx.x * 128 + tid;
    int p  = gi % HWp;
    int bt = gi / HWp;
    int b  = bt >> 3, t = bt & 7;

    const float* fb = first + (size_t)bt * CC * HWp + p;
    const float* xb = x     + (size_t)bt * CC * HWp + p;
    ull fp[16], xp[16];
    #pragma unroll
    for (int j = 0; j < 16; j++) {
        fp[j] = pack2(fb[(2*j)*HWp], fb[(2*j+1)*HWp]);
        xp[j] = pack2(xb[(2*j)*HWp], xb[(2*j+1)*HWp]);
    }

    #pragma unroll
    for (int h = 0; h < NHh; h++) {
        float kr[8], vr[8];
        #pragma unroll
        for (int c8 = 0; c8 < 8; c8++) {
            int o = h*8 + c8;
            const ull* wq = (const ull*)&swq[o*CC];
            const ull* wk = (const ull*)&swk[o*CC];
            const ull* wv = (const ull*)&swv[o*CC];
            ull aq = mul2(fp[0], wq[0]);
            ull ak = mul2(xp[0], wk[0]);
            ull av = mul2(xp[0], wv[0]);
            #pragma unroll
            for (int j = 1; j < 16; j++) {
                aq = fma2(fp[j], wq[j], aq);
                ak = fma2(xp[j], wk[j], ak);
                av = fma2(xp[j], wv[j], av);
            }
            float l, hh;
            unpack2(aq, l, hh);
            g_q[((size_t)bt*CC + o)*HWp + p] = l + hh;
            unpack2(ak, l, hh); kr[c8] = l + hh;
            unpack2(av, l, hh); vr[c8] = l + hh;
        }
        // plane-major write: 4 k-dup planes + 2 v planes, coalesced over p
        float4* dst = (float4*)g_kv + ((((size_t)b*NHh + h)*TT + t)*6)*HWp + p;
        #pragma unroll
        for (int j = 0; j < 4; j++)
            dst[j*HWp] = make_float4(kr[2*j], kr[2*j], kr[2*j+1], kr[2*j+1]);
        dst[4*HWp] = make_float4(vr[0], vr[1], vr[2], vr[3]);
        dst[5*HWp] = make_float4(vr[4], vr[5], vr[6], vr[7]);
    }
}

// ---------------- K2: per-(b,t,head) LayerNorm of q ----------------
__global__ __launch_bounds__(128)
void k_ln(const float* __restrict__ gamma, const float* __restrict__ beta) {
    const int N = DKk * HWp;                      // 3584
    float* base = g_q + (size_t)blockIdx.x * N;
    int tid = threadIdx.x;

    float vals[28];
    float s = 0.f, sq = 0.f;
    #pragma unroll
    for (int i = 0; i < 28; i++) {
        float v = base[tid + i*128];
        vals[i] = v; s += v; sq = fmaf(v, v, sq);
    }
    #pragma unroll
    for (int o = 16; o > 0; o >>= 1) {
        s  += __shfl_xor_sync(0xFFFFFFFFu, s,  o);
        sq += __shfl_xor_sync(0xFFFFFFFFu, sq, o);
    }
    __shared__ float shs[4], shq[4];
    if ((tid & 31) == 0) { shs[tid>>5] = s; shq[tid>>5] = sq; }
    __syncthreads();
    s  = shs[0]+shs[1]+shs[2]+shs[3];
    sq = shq[0]+shq[1]+shq[2]+shq[3];

    float mu   = s * (1.0f/3584.0f);
    float var  = fmaf(-mu, mu, sq * (1.0f/3584.0f));
    float rstd = rsqrtf(var + 1e-5f);
    #pragma unroll
    for (int i = 0; i < 28; i++) {
        int idx = tid + i*128;
        base[idx] = fmaf((vals[i]-mu)*rstd, gamma[idx], beta[idx]);
    }
}

// ---------------- K3: dilated local attention ----------------
// grid = 2048: bid = [b(3)][ts(1)][s(3)][head(2)][ys(2)]; warp = one y-row.
// Plane-major smem (no swizzle, LDS immediates), t-pair q vs dup-k (no
// horizontal add), MUFU ex2 for the softmax sum.
__global__ __launch_bounds__(128, 4)
void k_attn() {
    int bid  = blockIdx.x;
    int ys   = bid & 3;
    int head = (bid >> 2) & 3;
    int s    = (bid >> 4) & 7;
    int ts   = (bid >> 7) & 1;
    int b    = bid >> 8;
    const int dil = 2*head + 1;

    __shared__ float4 skv[6*PLN + 2];             // 6 planes, stride 449 (+zero slot)

    int tid  = threadIdx.x;
    int row  = tid >> 5;
    int lane = tid & 31;
    bool act = lane < WW;
    int xq   = lane;
    int y    = ys*4 + row;
    int p    = y*WW + (act ? xq : 0);
    int t0   = ts*4;

    {   // stage: gmem [plane(6)][448] -> smem plane stride 449
        const float4* src = (const float4*)g_kv +
            ((((size_t)b*NHh + head)*TT + s)*6)*HWp;
        #pragma unroll
        for (int r = 0; r < 21; r++) {
            int idx = tid + r*128;                // 0..2687
            int j   = idx / HWp;
            skv[idx + j] = src[idx];              // idx + j == j*449 + sp
        }
        if (tid < 6) skv[tid*PLN + HWp] = make_float4(0.f,0.f,0.f,0.f);
    }

    const float INV = 0.35355339059327373f;                 // 1/sqrt(C/NH)
    const float S2C = 0.35355339059327373f * 1.4426950408889634f;
    const ull S2_2 = pack2(S2C, S2C);
    const ull BV_V = pack2(-32.f, -32.f);
    const ull BV_I = pack2(-126.f, -126.f);

    // q t-pair packed: qA[c] = (q[t0][c], q[t0+1][c]), qB[c] = (q[t0+2][c], q[t0+3][c])
    ull qA[8], qB[8];
    #pragma unroll
    for (int c = 0; c < 8; c++) {
        size_t qb = ((size_t)(b*TT + t0)*CC + head*DKk + c)*HWp + p;
        float q0 = g_q[qb];
        float q1 = g_q[qb +   (size_t)CC*HWp];
        float q2 = g_q[qb + 2*(size_t)CC*HWp];
        float q3 = g_q[qb + 3*(size_t)CC*HWp];
        qA[c] = pack2(q0, q1);
        qB[c] = pack2(q2, q3);
    }

    ull tout[4][4];
    #pragma unroll
    for (int t = 0; t < 4; t++)
        #pragma unroll
        for (int j = 0; j < 4; j++) tout[t][j] = pack2(0.f, 0.f);
    float sum0=0.f, sum1=0.f, sum2=0.f, sum3=0.f;
    float mx0=-126.f, mx1=-126.f, mx2=-126.f, mx3=-126.f;

    const ulonglong2* pk0 = (const ulonglong2*)(skv);
    const ulonglong2* pk1 = (const ulonglong2*)(skv + PLN);
    const ulonglong2* pk2 = (const ulonglong2*)(skv + 2*PLN);
    const ulonglong2* pk3 = (const ulonglong2*)(skv + 3*PLN);
    const ulonglong2* pv0 = (const ulonglong2*)(skv + 4*PLN);
    const ulonglong2* pv1 = (const ulonglong2*)(skv + 5*PLN);
    __syncthreads();

    #pragma unroll 1
    for (int oy = -3; oy <= 3; oy++) {
        int yy = y + oy*dil;
        if ((unsigned)yy >= (unsigned)HH) continue;   // warp-uniform skip
        int rb = yy * WW;
        #pragma unroll 2
        for (int i = 0; i < 7; i++) {
            int xx = xq + (i - 3)*dil;
            bool vx = (unsigned)xx < (unsigned)WW;
            int sp  = vx ? (rb + xx) : HWp;           // HWp -> zero slot (k=v=0)
            ull bv2 = vx ? BV_V : BV_I;

            ulonglong2 k0 = pk0[sp];                  // (k0,k0),(k1,k1)
            ulonglong2 k1 = pk1[sp];                  // (k2,k2),(k3,k3)
            ulonglong2 k2 = pk2[sp];
            ulonglong2 k3 = pk3[sp];
            ulonglong2 v0 = pv0[sp];                  // (v0,v1),(v2,v3)
            ulonglong2 v1 = pv1[sp];                  // (v4,v5),(v6,v7)

            ull dA = mul2(qA[0], k0.x);
            ull dB = mul2(qB[0], k0.x);
            dA = fma2(qA[1], k0.y, dA);  dB = fma2(qB[1], k0.y, dB);
            dA = fma2(qA[2], k1.x, dA);  dB = fma2(qB[2], k1.x, dB);
            dA = fma2(qA[3], k1.y, dA);  dB = fma2(qB[3], k1.y, dB);
            dA = fma2(qA[4], k2.x, dA);  dB = fma2(qB[4], k2.x, dB);
            dA = fma2(qA[5], k2.y, dA);  dB = fma2(qB[5], k2.y, dB);
            dA = fma2(qA[6], k3.x, dA);  dB = fma2(qB[6], k3.x, dB);
            dA = fma2(qA[7], k3.y, dA);  dB = fma2(qB[7], k3.y, dB);

            // softmax side (MUFU)
            ull aA = fma2(dA, S2_2, bv2);
            ull aB = fma2(dB, S2_2, bv2);
            float a0,a1,a2,a3;
            unpack2(aA, a0, a1); unpack2(aB, a2, a3);
            sum0 += ex2f(a0); sum1 += ex2f(a1);
            sum2 += ex2f(a2); sum3 += ex2f(a3);
            mx0 = fmaxf(mx0, a0); mx1 = fmaxf(mx1, a1);
            mx2 = fmaxf(mx2, a2); mx3 = fmaxf(mx3, a3);

            // tout: raw score * v (INV folded out); masked k=0 -> w=0
            float w0,w1,w2,w3;
            unpack2(dA, w0, w1); unpack2(dB, w2, w3);
            ull wp0 = pack2(w0,w0), wp1 = pack2(w1,w1);
            ull wp2 = pack2(w2,w2), wp3 = pack2(w3,w3);
            tout[0][0] = fma2(wp0, v0.x, tout[0][0]);
            tout[1][0] = fma2(wp1, v0.x, tout[1][0]);
            tout[2][0] = fma2(wp2, v0.x, tout[2][0]);
            tout[3][0] = fma2(wp3, v0.x, tout[3][0]);
            tout[0][1] = fma2(wp0, v0.y, tout[0][1]);
            tout[1][1] = fma2(wp1, v0.y, tout[1][1]);
            tout[2][1] = fma2(wp2, v0.y, tout[2][1]);
            tout[3][1] = fma2(wp3, v0.y, tout[3][1]);
            tout[0][2] = fma2(wp0, v1.x, tout[0][2]);
            tout[1][2] = fma2(wp1, v1.x, tout[1][2]);
            tout[2][2] = fma2(wp2, v1.x, tout[2][2]);
            tout[3][2] = fma2(wp3, v1.x, tout[3][2]);
            tout[0][3] = fma2(wp0, v1.y, tout[0][3]);
            tout[1][3] = fma2(wp1, v1.y, tout[1][3]);
            tout[2][3] = fma2(wp2, v1.y, tout[2][3]);
            tout[3][3] = fma2(wp3, v1.y, tout[3][3]);
        }
    }

    if (act) {
        float su[4] = { sum0, sum1, sum2, sum3 };
        float mxv[4] = { mx0, mx1, mx2, mx3 };
        #pragma unroll
        for (int t = 0; t < 4; t++) {
            int bt = b*TT + t0 + t;
            float e[8];
            #pragma unroll
            for (int j = 0; j < 4; j++) unpack2(tout[t][j], e[2*j], e[2*j+1]);
            float* tb = g_tout + ((size_t)bt*CC + head*DKk)*HWp + p;
            #pragma unroll
            for (int c = 0; c < 8; c++) atomicAdd(tb + c*HWp, e[c] * INV);
            size_t mi = ((size_t)bt*NHh + head)*HWp + p;
            atomicAdd(g_sum + mi, su[t]);
            atomicMax(g_mx + mi, fmap(mxv[t]));
        }
    }
}

// ---------------- K4: M_S + output projection ----------------
__global__ __launch_bounds__(128)
void k_out(const float* __restrict__ Wo, float* __restrict__ out) {
    __shared__ float swo[1024];
    int tid = threadIdx.x;
    for (int i = tid; i < 1024; i += 128) swo[i] = Wo[i];
    __syncthreads();

    int gi = blockIdx.x * 128 + tid;              // [0, 57344)
    int p  = gi % HWp;
    int r  = gi / HWp;
    int bt = r >> 1;
    int oh = (r & 1) * 16;

    ull tc2[16];
    #pragma unroll
    for (int j = 0; j < 16; j++) {
        float a = g_tout[((size_t)bt*CC + 2*j    )*HWp + p];
        float b = g_tout[((size_t)bt*CC + 2*j + 1)*HWp + p];
        tc2[j] = pack2(a, b);
    }

    float MS = 0.f;
    #pragma unroll
    for (int h = 0; h < NHh; h++) {
        size_t mi = ((size_t)bt*NHh + h)*HWp + p;
        float s = g_sum[mi];
        float m = funmap(g_mx[mi]);
        MS = fmaxf(MS, __fdividef(exp2_fast(m), s));
    }

    float* ob = out + (size_t)bt * CC * HWp + p;
    #pragma unroll
    for (int o = oh; o < oh + 16; o++) {
        const ull* wp = (const ull*)&swo[o*CC];
        ull acc = mul2(tc2[0], wp[0]);
        #pragma unroll
        for (int j = 1; j < 16; j++) acc = fma2(tc2[j], wp[j], acc);
        float l, h; unpack2(acc, l, h);
        ob[o*HWp] = (l + h) * MS;
    }
}

// ---------------- launcher ----------------
extern "C" void kernel_launch(void* const* d_in, const int* in_sizes, int n_in,
                              void* d_out, int out_size) {
    const float* first = (const float*)d_in[0];
    const float* x     = (const float*)d_in[1];
    const float* Wq    = (const float*)d_in[2];
    const float* Wk    = (const float*)d_in[3];
    const float* Wv    = (const float*)d_in[4];
    const float* Wo    = (const float*)d_in[5];
    const float* lng   = (const float*)d_in[6];
    const float* lnb   = (const float*)d_in[7];
    float* out = (float*)d_out;

    k_init<<<296, 256>>>();
    k_proj<<<224, 128>>>(first, x, Wq, Wk, Wv);
    k_ln<<<BB*TT*NHh, 128>>>(lng, lnb);
    k_attn<<<2048, 128>>>();
    k_out<<<448, 128>>>(Wo, out);
}

// round 8
// speedup vs baseline: 1.5140x; 1.0476x over previous
#include <cuda_runtime.h>

typedef unsigned long long ull;

// ---------------- problem constants ----------------
#define BB   8
#define TT   8
#define CC   32
#define HH   16
#define WW   28
#define HWp  448
#define NHh  4
#define DKk  8
#define PLN  449               // smem plane stride in 16B granules (448 + zero slot)

// ---------------- device scratch ----------------
__device__ __align__(16) float g_q   [BB*TT*CC*HWp];          // [bt][o][p]
// kv plane-major: [b][h][s][plane(4)][448] float4
//   plane0: (k0,k1,k2,k3)  plane1: (k4..k7)  plane2: (v0..v3)  plane3: (v4..v7)
__device__ __align__(16) float g_kv  [BB*NHh*TT*4*HWp*4];
__device__ __align__(16) float g_tout[BB*TT*CC*HWp];          // combined [bt][h*8+c][p]
__device__ __align__(16) float g_sum [BB*TT*NHh*HWp];         // combined [bt][h][p]
__device__ __align__(16) unsigned g_mx[BB*TT*NHh*HWp];        // monotonic-mapped max

#define TOUTN (BB*TT*CC*HWp)
#define SUMN  (BB*TT*NHh*HWp)

// ---------------- packed f32x2 helpers ----------------
__device__ __forceinline__ ull pack2(float lo, float hi){ ull r; asm("mov.b64 %0,{%1,%2};":"=l"(r):"f"(lo),"f"(hi)); return r; }
__device__ __forceinline__ void unpack2(ull v, float& lo, float& hi){ asm("mov.b64 {%0,%1},%2;":"=f"(lo),"=f"(hi):"l"(v)); }
__device__ __forceinline__ ull fma2(ull a, ull b, ull c){ ull d; asm("fma.rn.f32x2 %0,%1,%2,%3;":"=l"(d):"l"(a),"l"(b),"l"(c)); return d; }
__device__ __forceinline__ ull add2(ull a, ull b){ ull d; asm("add.rn.f32x2 %0,%1,%2;":"=l"(d):"l"(a),"l"(b)); return d; }
__device__ __forceinline__ ull mul2(ull a, ull b){ ull d; asm("mul.rn.f32x2 %0,%1,%2;":"=l"(d):"l"(a),"l"(b)); return d; }
__device__ __forceinline__ float ex2f(float x){ float y; asm("ex2.approx.f32 %0,%1;":"=f"(y):"f"(x)); return y; }

__device__ __forceinline__ float exp2_fast(float x) {   // k_out only
    float z = __fadd_rn(x, 12582912.0f);
    float n = __fadd_rn(z, -12582912.0f);
    float f = x - n;
    int   sb = __float_as_int(z) * 8388608 + 0x3F800000;
    float p = fmaf(fmaf(fmaf(fmaf(0.0096181291f, f, 0.055504109f),
                             f, 0.24022651f), f, 0.69314718f), f, 1.0f);
    return p * __int_as_float(sb);
}

// monotonic float->uint map
__device__ __forceinline__ unsigned fmap(float f) {
    unsigned u = __float_as_uint(f);
    return (u & 0x80000000u) ? ~u : (u | 0x80000000u);
}
__device__ __forceinline__ float funmap(unsigned m) {
    return (m & 0x80000000u) ? __uint_as_float(m ^ 0x80000000u)
                             : __uint_as_float(~m);
}

// ---------------- K0: init combine buffers ----------------
__global__ __launch_bounds__(256)
void k_init() {
    int i = blockIdx.x * 256 + threadIdx.x;
    int stride = gridDim.x * 256;
    for (int j = i; j < TOUTN/4; j += stride) ((float4*)g_tout)[j] = make_float4(0.f,0.f,0.f,0.f);
    for (int j = i; j < SUMN/4;  j += stride) ((float4*)g_sum)[j]  = make_float4(0.f,0.f,0.f,0.f);
    for (int j = i; j < SUMN/4;  j += stride) ((uint4*)g_mx)[j]    = make_uint4(0u,0u,0u,0u);
}

// ---------------- K1: Q/K/V projections ----------------
__global__ __launch_bounds__(128)
void k_proj(const float* __restrict__ first, const float* __restrict__ x,
            const float* __restrict__ Wq, const float* __restrict__ Wk,
            const float* __restrict__ Wv) {
    __shared__ float swq[1024], swk[1024], swv[1024];
    int tid = threadIdx.x;
    for (int i = tid; i < 1024; i += 128) { swq[i]=Wq[i]; swk[i]=Wk[i]; swv[i]=Wv[i]; }
    __syncthreads();

    int gi = blockIdx.x * 128 + tid;
    int p  = gi % HWp;
    int bt = gi / HWp;
    int b  = bt >> 3, t = bt & 7;

    const float* fb = first + (size_t)bt * CC * HWp + p;
    const float* xb = x     + (size_t)bt * CC * HWp + p;
    ull fp[16], xp[16];
    #pragma unroll
    for (int j = 0; j < 16; j++) {
        fp[j] = pack2(fb[(2*j)*HWp], fb[(2*j+1)*HWp]);
        xp[j] = pack2(xb[(2*j)*HWp], xb[(2*j+1)*HWp]);
    }

    #pragma unroll
    for (int h = 0; h < NHh; h++) {
        float kr[8], vr[8];
        #pragma unroll
        for (int c8 = 0; c8 < 8; c8++) {
            int o = h*8 + c8;
            const ull* wq = (const ull*)&swq[o*CC];
            const ull* wk = (const ull*)&swk[o*CC];
            const ull* wv = (const ull*)&swv[o*CC];
            ull aq = mul2(fp[0], wq[0]);
            ull ak = mul2(xp[0], wk[0]);
            ull av = mul2(xp[0], wv[0]);
            #pragma unroll
            for (int j = 1; j < 16; j++) {
                aq = fma2(fp[j], wq[j], aq);
                ak = fma2(xp[j], wk[j], ak);
                av = fma2(xp[j], wv[j], av);
            }
            float l, hh;
            unpack2(aq, l, hh);
            g_q[((size_t)bt*CC + o)*HWp + p] = l + hh;
            unpack2(ak, l, hh); kr[c8] = l + hh;
            unpack2(av, l, hh); vr[c8] = l + hh;
        }
        // plane-major write: 2 k planes + 2 v planes, coalesced over p
        float4* dst = (float4*)g_kv + ((((size_t)b*NHh + h)*TT + t)*4)*HWp + p;
        dst[0*HWp] = make_float4(kr[0], kr[1], kr[2], kr[3]);
        dst[1*HWp] = make_float4(kr[4], kr[5], kr[6], kr[7]);
        dst[2*HWp] = make_float4(vr[0], vr[1], vr[2], vr[3]);
        dst[3*HWp] = make_float4(vr[4], vr[5], vr[6], vr[7]);
    }
}

// ---------------- K2: per-(b,t,head) LayerNorm of q ----------------
__global__ __launch_bounds__(128)
void k_ln(const float* __restrict__ gamma, const float* __restrict__ beta) {
    const int N = DKk * HWp;                      // 3584
    float* base = g_q + (size_t)blockIdx.x * N;
    int tid = threadIdx.x;

    float vals[28];
    float s = 0.f, sq = 0.f;
    #pragma unroll
    for (int i = 0; i < 28; i++) {
        float v = base[tid + i*128];
        vals[i] = v; s += v; sq = fmaf(v, v, sq);
    }
    #pragma unroll
    for (int o = 16; o > 0; o >>= 1) {
        s  += __shfl_xor_sync(0xFFFFFFFFu, s,  o);
        sq += __shfl_xor_sync(0xFFFFFFFFu, sq, o);
    }
    __shared__ float shs[4], shq[4];
    if ((tid & 31) == 0) { shs[tid>>5] = s; shq[tid>>5] = sq; }
    __syncthreads();
    s  = shs[0]+shs[1]+shs[2]+shs[3];
    sq = shq[0]+shq[1]+shq[2]+shq[3];

    float mu   = s * (1.0f/3584.0f);
    float var  = fmaf(-mu, mu, sq * (1.0f/3584.0f));
    float rstd = rsqrtf(var + 1e-5f);
    #pragma unroll
    for (int i = 0; i < 28; i++) {
        int idx = tid + i*128;
        base[idx] = fmaf((vals[i]-mu)*rstd, gamma[idx], beta[idx]);
    }
}

// ---------------- K3: dilated local attention ----------------
// grid = 2048: bid = [b(3)][ts(1)][s(3)][head(2)][ys(2)]; warp = one y-row
// (warp-uniform oy skip). Plane-major smem, c-pair k (4 LDS.128/offset),
// MUFU ex2 softmax. Idle lanes 28..31 mirror lane 27 (no extra crossbar).
__global__ __launch_bounds__(128, 4)
void k_attn() {
    int bid  = blockIdx.x;
    int ys   = bid & 3;
    int head = (bid >> 2) & 3;
    int s    = (bid >> 4) & 7;
    int ts   = (bid >> 7) & 1;
    int b    = bid >> 8;
    const int dil = 2*head + 1;

    __shared__ float4 skv[4*PLN + 4];             // 4 planes, stride 449 (+zero slot)

    int tid  = threadIdx.x;
    int row  = tid >> 5;
    int lane = tid & 31;
    bool act = lane < WW;
    int xq   = act ? lane : 27;                   // idle lanes mirror lane 27
    int y    = ys*4 + row;
    int p    = y*WW + xq;
    int t0   = ts*4;

    {   // stage: gmem [plane(4)][448] -> smem plane stride 449
        const float4* src = (const float4*)g_kv +
            ((((size_t)b*NHh + head)*TT + s)*4)*HWp;
        #pragma unroll
        for (int r = 0; r < 14; r++) {
            int idx = tid + r*128;                // 0..1791
            int j   = idx / HWp;
            skv[idx + j] = src[idx];              // == j*449 + sp
        }
        if (tid < 4) skv[tid*PLN + HWp] = make_float4(0.f,0.f,0.f,0.f);
    }

    const float INV = 0.35355339059327373f;                 // 1/sqrt(C/NH)
    const float S2C = 0.35355339059327373f * 1.4426950408889634f;

    // q c-pair packed per timestep
    ull qp[4][4];
    #pragma unroll
    for (int t = 0; t < 4; t++) {
        const float* qb = g_q + ((size_t)(b*TT + t0 + t)*CC + head*DKk)*HWp + p;
        #pragma unroll
        for (int j = 0; j < 4; j++)
            qp[t][j] = pack2(qb[(2*j)*HWp], qb[(2*j+1)*HWp]);
    }

    ull tout[4][4];
    #pragma unroll
    for (int t = 0; t < 4; t++)
        #pragma unroll
        for (int j = 0; j < 4; j++) tout[t][j] = pack2(0.f, 0.f);
    float sum0=0.f, sum1=0.f, sum2=0.f, sum3=0.f;
    float mx0=-126.f, mx1=-126.f, mx2=-126.f, mx3=-126.f;

    const ulonglong2* pk0 = (const ulonglong2*)(skv);
    const ulonglong2* pk1 = (const ulonglong2*)(skv + PLN);
    const ulonglong2* pv0 = (const ulonglong2*)(skv + 2*PLN);
    const ulonglong2* pv1 = (const ulonglong2*)(skv + 3*PLN);
    __syncthreads();

    #pragma unroll 1
    for (int oy = -3; oy <= 3; oy++) {
        int yy = y + oy*dil;
        if ((unsigned)yy >= (unsigned)HH) continue;   // warp-uniform skip
        int rb = yy * WW;
        #pragma unroll 2
        for (int i = 0; i < 7; i++) {
            int xx = xq + (i - 3)*dil;
            bool vx = (unsigned)xx < (unsigned)WW;
            int sp  = vx ? (rb + xx) : HWp;           // HWp -> zero slot (k=v=0)
            float bv = vx ? -32.f : -126.f;

            ulonglong2 k0 = pk0[sp];                  // (k0,k1),(k2,k3)
            ulonglong2 k1 = pk1[sp];                  // (k4,k5),(k6,k7)
            ulonglong2 v0 = pv0[sp];                  // (v0,v1),(v2,v3)
            ulonglong2 v1 = pv1[sp];                  // (v4,v5),(v6,v7)

            // dot per timestep (c-pair), then horizontal add
            ull d0 = mul2(qp[0][0], k0.x);
            ull d1 = mul2(qp[1][0], k0.x);
            ull d2 = mul2(qp[2][0], k0.x);
            ull d3 = mul2(qp[3][0], k0.x);
            d0 = fma2(qp[0][1], k0.y, d0); d1 = fma2(qp[1][1], k0.y, d1);
            d2 = fma2(qp[2][1], k0.y, d2); d3 = fma2(qp[3][1], k0.y, d3);
            d0 = fma2(qp[0][2], k1.x, d0); d1 = fma2(qp[1][2], k1.x, d1);
            d2 = fma2(qp[2][2], k1.x, d2); d3 = fma2(qp[3][2], k1.x, d3);
            d0 = fma2(qp[0][3], k1.y, d0); d1 = fma2(qp[1][3], k1.y, d1);
            d2 = fma2(qp[2][3], k1.y, d2); d3 = fma2(qp[3][3], k1.y, d3);

            float l0,h0,l1,h1,l2,h2,l3,h3;
            unpack2(d0,l0,h0); unpack2(d1,l1,h1);
            unpack2(d2,l2,h2); unpack2(d3,l3,h3);
            float sc0 = l0+h0, sc1 = l1+h1, sc2 = l2+h2, sc3 = l3+h3;

            // softmax side (MUFU)
            float a0 = fmaf(sc0, S2C, bv);
            float a1 = fmaf(sc1, S2C, bv);
            float a2 = fmaf(sc2, S2C, bv);
            float a3 = fmaf(sc3, S2C, bv);
            sum0 += ex2f(a0); sum1 += ex2f(a1);
            sum2 += ex2f(a2); sum3 += ex2f(a3);
            mx0 = fmaxf(mx0, a0); mx1 = fmaxf(mx1, a1);
            mx2 = fmaxf(mx2, a2); mx3 = fmaxf(mx3, a3);

            // tout: raw score * v (INV folded out); masked k=0 -> w=0
            ull wp0 = pack2(sc0,sc0), wp1 = pack2(sc1,sc1);
            ull wp2 = pack2(sc2,sc2), wp3 = pack2(sc3,sc3);
            tout[0][0] = fma2(wp0, v0.x, tout[0][0]);
            tout[1][0] = fma2(wp1, v0.x, tout[1][0]);
            tout[2][0] = fma2(wp2, v0.x, tout[2][0]);
            tout[3][0] = fma2(wp3, v0.x, tout[3][0]);
            tout[0][1] = fma2(wp0, v0.y, tout[0][1]);
            tout[1][1] = fma2(wp1, v0.y, tout[1][1]);
            tout[2][1] = fma2(wp2, v0.y, tout[2][1]);
            tout[3][1] = fma2(wp3, v0.y, tout[3][1]);
            tout[0][2] = fma2(wp0, v1.x, tout[0][2]);
            tout[1][2] = fma2(wp1, v1.x, tout[1][2]);
            tout[2][2] = fma2(wp2, v1.x, tout[2][2]);
            tout[3][2] = fma2(wp3, v1.x, tout[3][2]);
            tout[0][3] = fma2(wp0, v1.y, tout[0][3]);
            tout[1][3] = fma2(wp1, v1.y, tout[1][3]);
            tout[2][3] = fma2(wp2, v1.y, tout[2][3]);
            tout[3][3] = fma2(wp3, v1.y, tout[3][3]);
        }
    }

    if (act) {
        float su[4] = { sum0, sum1, sum2, sum3 };
        float mxv[4] = { mx0, mx1, mx2, mx3 };
        #pragma unroll
        for (int t = 0; t < 4; t++) {
            int bt = b*TT + t0 + t;
            float e[8];
            #pragma unroll
            for (int j = 0; j < 4; j++) unpack2(tout[t][j], e[2*j], e[2*j+1]);
            float* tb = g_tout + ((size_t)bt*CC + head*DKk)*HWp + p;
            #pragma unroll
            for (int c = 0; c < 8; c++) atomicAdd(tb + c*HWp, e[c] * INV);
            size_t mi = ((size_t)bt*NHh + head)*HWp + p;
            atomicAdd(g_sum + mi, su[t]);
            atomicMax(g_mx + mi, fmap(mxv[t]));
        }
    }
}

// ---------------- K4: M_S + output projection (o split 4 ways) ----------------
__global__ __launch_bounds__(128)
void k_out(const float* __restrict__ Wo, float* __restrict__ out) {
    __shared__ float swo[1024];
    int tid = threadIdx.x;
    for (int i = tid; i < 1024; i += 128) swo[i] = Wo[i];
    __syncthreads();

    int gi = blockIdx.x * 128 + tid;              // [0, 114688)
    int p  = gi % HWp;
    int r  = gi / HWp;                            // [0, 256)
    int bt = r >> 2;
    int oh = (r & 3) * 8;

    ull tc2[16];
    #pragma unroll
    for (int j = 0; j < 16; j++) {
        float a = g_tout[((size_t)bt*CC + 2*j    )*HWp + p];
        float b = g_tout[((size_t)bt*CC + 2*j + 1)*HWp + p];
        tc2[j] = pack2(a, b);
    }

    float MS = 0.f;
    #pragma unroll
    for (int h = 0; h < NHh; h++) {
        size_t mi = ((size_t)bt*NHh + h)*HWp + p;
        float s = g_sum[mi];
        float m = funmap(g_mx[mi]);
        MS = fmaxf(MS, __fdividef(exp2_fast(m), s));
    }

    float* ob = out + (size_t)bt * CC * HWp + p;
    #pragma unroll
    for (int o = oh; o < oh + 8; o++) {
        const ull* wp = (const ull*)&swo[o*CC];
        ull acc = mul2(tc2[0], wp[0]);
        #pragma unroll
        for (int j = 1; j < 16; j++) acc = fma2(tc2[j], wp[j], acc);
        float l, h; unpack2(acc, l, h);
        ob[o*HWp] = (l + h) * MS;
    }
}

// ---------------- launcher ----------------
extern "C" void kernel_launch(void* const* d_in, const int* in_sizes, int n_in,
                              void* d_out, int out_size) {
    const float* first = (const float*)d_in[0];
    const float* x     = (const float*)d_in[1];
    const float* Wq    = (const float*)d_in[2];
    const float* Wk    = (const float*)d_in[3];
    const float* Wv    = (const float*)d_in[4];
    const float* Wo    = (const float*)d_in[5];
    const float* lng   = (const float*)d_in[6];
    const float* lnb   = (const float*)d_in[7];
    float* out = (float*)d_out;

    k_init<<<296, 256>>>();
    k_proj<<<224, 128>>>(first, x, Wq, Wk, Wv);
    k_ln<<<BB*TT*NHh, 128>>>(lng, lnb);
    k_attn<<<2048, 128>>>();
    k_out<<<896, 128>>>(Wo, out);
}